// round 4
// baseline (speedup 1.0000x reference)
#include <cuda_runtime.h>
#include <math.h>

#define BB 2
#define CC 256
#define HWN 6400
#define DD 32
#define PP 9
#define JSPLIT 4

// ---------------- device scratch ----------------
__device__ float g_qn_hi[BB*DD*HWN];
__device__ float g_qn_lo[BB*DD*HWN];
__device__ float g_kn_hi[BB*DD*HWN];
__device__ float g_kn_lo[BB*DD*HWN];
__device__ float g_v [BB*HWN*DD];            // [b][j][d]
__device__ float g_pval[BB*JSPLIT*HWN*PP];
__device__ int   g_pidx[BB*JSPLIT*HWN*PP];
__device__ float g_ovb[BB*HWN*CC];           // [b][n][c]

// ---------------- helpers ----------------
__device__ __forceinline__ float tf32r(float x) {
  unsigned y; asm("cvt.rna.tf32.f32 %0, %1;" : "=r"(y) : "f"(x));
  return __uint_as_float(y);
}
__device__ __forceinline__ void mma_tf32(
    float& c0, float& c1, float& c2, float& c3,
    unsigned a0, unsigned a1, unsigned a2, unsigned a3,
    unsigned b0, unsigned b1) {
  asm volatile("mma.sync.aligned.m16n8k8.row.col.f32.tf32.tf32.f32 "
    "{%0,%1,%2,%3},{%4,%5,%6,%7},{%8,%9},{%0,%1,%2,%3};"
    : "+f"(c0), "+f"(c1), "+f"(c2), "+f"(c3)
    : "r"(a0), "r"(a1), "r"(a2), "r"(a3), "r"(b0), "r"(b1));
}

// ---------------- K1: q,k,v projections + L2 normalize + tf32 split ----------------
__global__ void __launch_bounds__(256) proj_kernel(
    const float* __restrict__ feat, const float* __restrict__ Wq,
    const float* __restrict__ Wk,   const float* __restrict__ Wv) {
  __shared__ float xs[64][33];
  __shared__ float ws[96][64];
  __shared__ float outs[96][33];
  __shared__ float scl[2][32];
  int blk = blockIdx.x;
  int b  = blk / 200;
  int n0 = (blk % 200) * 32;
  int t  = threadIdx.x;
  int n  = t & 31, dg = t >> 5;
  float acc[12];
#pragma unroll
  for (int u = 0; u < 12; u++) acc[u] = 0.f;

  for (int c0 = 0; c0 < CC; c0 += 64) {
#pragma unroll
    for (int r = 0; r < 8; r++) {
      int e = t + 256*r; int cl = e >> 5, nn = e & 31;
      xs[cl][nn] = feat[(b*CC + c0 + cl)*HWN + n0 + nn];
    }
#pragma unroll
    for (int r = 0; r < 24; r++) {
      int e = t + 256*r; int cl = e & 63, d = e >> 6;
      const float* Wp = (d < 32) ? Wq : ((d < 64) ? Wk : Wv);
      ws[d][cl] = Wp[(d & 31)*CC + c0 + cl];
    }
    __syncthreads();
#pragma unroll 4
    for (int cl = 0; cl < 64; cl += 4) {
      float x0 = xs[cl][n], x1 = xs[cl+1][n], x2 = xs[cl+2][n], x3 = xs[cl+3][n];
#pragma unroll
      for (int u = 0; u < 12; u++) {
        const float4 w4 = *(const float4*)&ws[dg*12+u][cl];
        acc[u] += w4.x*x0 + w4.y*x1 + w4.z*x2 + w4.w*x3;
      }
    }
    __syncthreads();
  }
#pragma unroll
  for (int u = 0; u < 12; u++) outs[dg*12+u][n] = acc[u];
  __syncthreads();
  if (t < 64) {
    int nn = t & 31, wh = t >> 5;
    float s = 0.f;
#pragma unroll
    for (int d = 0; d < 32; d++) { float v = outs[wh*32+d][nn]; s += v*v; }
    scl[wh][nn] = 1.f / fmaxf(sqrtf(s), 1e-12f);
  }
  __syncthreads();
#pragma unroll
  for (int r = 0; r < 4; r++) {
    int e = t + 256*r; int d = e >> 5, nn = e & 31;
    float qv = outs[d][nn]    * scl[0][nn];
    float kv = outs[32+d][nn] * scl[1][nn];
    float qh = tf32r(qv), kh = tf32r(kv);
    int off = (b*DD + d)*HWN + n0 + nn;
    g_qn_hi[off] = qh; g_qn_lo[off] = tf32r(qv - qh);
    g_kn_hi[off] = kh; g_kn_lo[off] = tf32r(kv - kh);
  }
#pragma unroll
  for (int r = 0; r < 4; r++) {
    int e = t + 256*r; int d = e & 31, nn = e >> 5;
    g_v[(b*HWN + n0 + nn)*DD + d] = outs[64+d][nn];
  }
}

// ---------------- K2: w = qn @ kn^T (3xTF32 mma) fused top-9 ----------------
// grid: b(2) x split(4) x 100 i-tiles of 64. Each block scans 25 j-tiles of 64.
__global__ void __launch_bounds__(256) wtopk_kernel() {
  __shared__ float ks_hi[32][72];
  __shared__ float ks_lo[32][72];
  __shared__ float w_s[64][65];
  int blk = blockIdx.x;
  int b = blk / (JSPLIT*100); int rem = blk % (JSPLIT*100);
  int split = rem / 100; int i0 = (rem % 100) * 64;
  int t = threadIdx.x;
  int warp = t >> 5, lane = t & 31;
  int wi = warp & 1, wj = warp >> 1;     // 2 x 4 warp grid
  int g = lane >> 2, t4 = lane & 3;

  // stage qn tile (hi/lo) into ks buffers, then load persistent A fragments
#pragma unroll
  for (int r = 0; r < 8; r++) {
    int e = t + 256*r; int i = e & 63, d = e >> 6;
    int off = (b*DD + d)*HWN + i0 + i;
    ks_hi[d][i] = g_qn_hi[off];
    ks_lo[d][i] = g_qn_lo[off];
  }
  __syncthreads();
  unsigned Ah[2][4][4], Al[2][4][4];
#pragma unroll
  for (int m = 0; m < 2; m++) {
    int ib = wi*32 + m*16;
#pragma unroll
    for (int kt = 0; kt < 4; kt++) {
      int kb = kt*8;
      Ah[m][kt][0] = __float_as_uint(ks_hi[kb+t4  ][ib+g  ]);
      Ah[m][kt][1] = __float_as_uint(ks_hi[kb+t4  ][ib+g+8]);
      Ah[m][kt][2] = __float_as_uint(ks_hi[kb+t4+4][ib+g  ]);
      Ah[m][kt][3] = __float_as_uint(ks_hi[kb+t4+4][ib+g+8]);
      Al[m][kt][0] = __float_as_uint(ks_lo[kb+t4  ][ib+g  ]);
      Al[m][kt][1] = __float_as_uint(ks_lo[kb+t4  ][ib+g+8]);
      Al[m][kt][2] = __float_as_uint(ks_lo[kb+t4+4][ib+g  ]);
      Al[m][kt][3] = __float_as_uint(ks_lo[kb+t4+4][ib+g+8]);
    }
  }
  __syncthreads();

  float tv[9]; int ti[9];
#pragma unroll
  for (int s = 0; s < 9; s++) { tv[s] = -4.f; ti[s] = 0x7fffffff; }
  int srow = t & 63, strip = t >> 6;

  for (int jt = 0; jt < 100/JSPLIT; jt++) {
    int j0 = (split*(100/JSPLIT) + jt)*64;
#pragma unroll
    for (int r = 0; r < 8; r++) {
      int e = t + 256*r; int j = e & 63, d = e >> 6;
      int off = (b*DD + d)*HWN + j0 + j;
      ks_hi[d][j] = g_kn_hi[off];
      ks_lo[d][j] = g_kn_lo[off];
    }
    __syncthreads();
#pragma unroll
    for (int n = 0; n < 2; n++) {
      int jb = wj*16 + n*8;
      unsigned Bh[4][2], Bl[4][2];
#pragma unroll
      for (int kt = 0; kt < 4; kt++) {
        Bh[kt][0] = __float_as_uint(ks_hi[kt*8+t4  ][jb+g]);
        Bh[kt][1] = __float_as_uint(ks_hi[kt*8+t4+4][jb+g]);
        Bl[kt][0] = __float_as_uint(ks_lo[kt*8+t4  ][jb+g]);
        Bl[kt][1] = __float_as_uint(ks_lo[kt*8+t4+4][jb+g]);
      }
#pragma unroll
      for (int m = 0; m < 2; m++) {
        float c0=0.f, c1=0.f, c2=0.f, c3=0.f;
#pragma unroll
        for (int kt = 0; kt < 4; kt++) {
          mma_tf32(c0,c1,c2,c3, Al[m][kt][0],Al[m][kt][1],Al[m][kt][2],Al[m][kt][3], Bh[kt][0],Bh[kt][1]);
          mma_tf32(c0,c1,c2,c3, Ah[m][kt][0],Ah[m][kt][1],Ah[m][kt][2],Ah[m][kt][3], Bl[kt][0],Bl[kt][1]);
          mma_tf32(c0,c1,c2,c3, Ah[m][kt][0],Ah[m][kt][1],Ah[m][kt][2],Ah[m][kt][3], Bh[kt][0],Bh[kt][1]);
        }
        int rr = wi*32 + m*16 + g;
        int cb = jb + 2*t4;
        w_s[rr  ][cb] = c0; w_s[rr  ][cb+1] = c1;
        w_s[rr+8][cb] = c2; w_s[rr+8][cb+1] = c3;
      }
    }
    __syncthreads();
    // scan: thread owns (row, 16-col strip)
#pragma unroll
    for (int c = 0; c < 16; c++) {
      float v = w_s[srow][strip*16 + c];
      if (v > tv[8]) {
        float cv = v; int cj = j0 + strip*16 + c;
#pragma unroll
        for (int s = 0; s < 9; s++) {
          bool gt = cv > tv[s];
          float nv = gt ? cv : tv[s]; int ni = gt ? cj : ti[s];
          float sv = gt ? tv[s] : cv; int si = gt ? ti[s] : cj;
          tv[s] = nv; ti[s] = ni; cv = sv; cj = si;
        }
      }
    }
    __syncthreads();
  }
  // merge 4 strips per row
  float* sval = &ks_hi[0][0];
  int*   sidx = (int*)&ks_lo[0][0];
#pragma unroll
  for (int s = 0; s < 9; s++) {
    sval[(strip*64 + srow)*9 + s] = tv[s];
    sidx[(strip*64 + srow)*9 + s] = ti[s];
  }
  __syncthreads();
  if (t < 64) {
    float mv[9]; int mi[9];
#pragma unroll
    for (int s = 0; s < 9; s++) { mv[s] = -4.f; mi[s] = 0x7fffffff; }
    for (int sp = 0; sp < 4; sp++) {
      for (int q = 0; q < 9; q++) {
        float v = sval[(sp*64 + t)*9 + q];
        int   j = sidx[(sp*64 + t)*9 + q];
        if (v < mv[8]) break;
        if (v > mv[8] || (v == mv[8] && j < mi[8])) {
          float cv = v; int cj = j;
#pragma unroll
          for (int s = 0; s < 9; s++) {
            bool bt = (cv > mv[s]) || (cv == mv[s] && cj < mi[s]);
            float nv = bt ? cv : mv[s]; int ni = bt ? cj : mi[s];
            float ov_ = bt ? mv[s] : cv; int oi = bt ? mi[s] : cj;
            mv[s]=nv; mi[s]=ni; cv=ov_; cj=oi;
          }
        }
      }
    }
    int row = i0 + t;
#pragma unroll
    for (int s = 0; s < 9; s++) {
      g_pval[((b*JSPLIT + split)*HWN + row)*PP + s] = mv[s];
      g_pidx[((b*JSPLIT + split)*HWN + row)*PP + s] = mi[s];
    }
  }
}

// ---------------- K3: merge splits + gate MLP + softmax + gather + back ----------------
__global__ void __launch_bounds__(256) post_kernel(
    const float* __restrict__ adw, const float* __restrict__ adb,
    const float* __restrict__ pw1, const float* __restrict__ pw2,
    const float* __restrict__ back_w, const float* __restrict__ catt) {
  __shared__ float back_s[256][33];
  __shared__ float w1s[162];
  __shared__ float w2s[162];
  __shared__ float wfin_s[8][12];
  __shared__ int   idx_s[8][12];
  int blk = blockIdx.x;
  int b = blk / 800;
  int row0 = (blk % 800) * 8;
  int t = threadIdx.x;
#pragma unroll
  for (int r = 0; r < 32; r++) {
    int e = t + 256*r; int c = e >> 5, d = e & 31;
    back_s[c][d] = back_w[c*DD + d];
  }
  if (t < 162) { w1s[t] = pw1[t]; w2s[t] = pw2[t]; }
  __syncthreads();
  int wrp = t >> 5, lane = t & 31;
  int row = row0 + wrp;

  if (lane == 0) {
    float mv[9]; int mi[9];
#pragma unroll
    for (int s = 0; s < 9; s++) { mv[s] = -4.f; mi[s] = 0x7fffffff; }
    for (int sp = 0; sp < JSPLIT; sp++) {
      for (int q = 0; q < 9; q++) {
        float v = g_pval[((b*JSPLIT + sp)*HWN + row)*PP + q];
        int   j = g_pidx[((b*JSPLIT + sp)*HWN + row)*PP + q];
        if (v < mv[8]) break;
        if (v > mv[8] || (v == mv[8] && j < mi[8])) {
          float cv = v; int cj = j;
#pragma unroll
          for (int s = 0; s < 9; s++) {
            bool bt = (cv > mv[s]) || (cv == mv[s] && cj < mi[s]);
            float nv = bt ? cv : mv[s]; int ni = bt ? cj : mi[s];
            float ov_ = bt ? mv[s] : cv; int oi = bt ? mi[s] : cj;
            mv[s]=nv; mi[s]=ni; cv=ov_; cj=oi;
          }
        }
      }
    }
    float adwv = adw[0], adbv = adb[0];
    float xa[9], pos[9];
#pragma unroll
    for (int p = 0; p < 9; p++) { xa[p] = mv[p]*adwv + adbv; pos[p] = fmaxf(xa[p], 0.f); }
    float hdn[18];
#pragma unroll
    for (int q = 0; q < 18; q++) {
      float s = 0.f;
#pragma unroll
      for (int p = 0; p < 9; p++) s += w1s[q*9+p]*pos[p];
      hdn[q] = fmaxf(s, 0.f);
    }
    float z[9]; float zmax = -1e30f;
#pragma unroll
    for (int p = 0; p < 9; p++) { z[p] = (xa[p] > 0.f) ? xa[p] : -100000.0f; zmax = fmaxf(zmax, z[p]); }
    float es[9]; float esum = 0.f;
#pragma unroll
    for (int p = 0; p < 9; p++) { es[p] = expf(z[p]-zmax); esum += es[p]; }
    float inv = 1.f/esum;
#pragma unroll
    for (int p = 0; p < 9; p++) {
      float s = 0.f;
#pragma unroll
      for (int q = 0; q < 18; q++) s += w2s[p*18+q]*hdn[q];
      float msk = 1.f/(1.f+expf(-s));
      wfin_s[wrp][p] = es[p]*inv*msk;
      idx_s[wrp][p]  = mi[p];
    }
  }
  __syncwarp();
  float ov = 0.f;
#pragma unroll
  for (int p = 0; p < 9; p++)
    ov += wfin_s[wrp][p] * g_v[(b*HWN + idx_s[wrp][p])*DD + lane];
  float outc[8];
#pragma unroll
  for (int cc = 0; cc < 8; cc++) outc[cc] = 0.f;
#pragma unroll
  for (int d = 0; d < 32; d++) {
    float ovd = __shfl_sync(0xffffffffu, ov, d);
#pragma unroll
    for (int cc = 0; cc < 8; cc++) outc[cc] += back_s[cc*32+lane][d]*ovd;
  }
#pragma unroll
  for (int cc = 0; cc < 8; cc++) {
    int c = cc*32 + lane;
    g_ovb[(b*HWN + row)*CC + c] = outc[cc]*catt[c];
  }
}

// ---------------- K4: mlp GEMM (3xTF32 mma) + bias + BN + relu ----------------
__global__ void __launch_bounds__(256) mlp_kernel(
    const float* __restrict__ feat, const float* __restrict__ mlp_w,
    const float* __restrict__ mlp_b, const float* __restrict__ mlp_gamma,
    const float* __restrict__ mlp_beta, const float* __restrict__ catt1,
    float* __restrict__ xout) {
  __shared__ float a_hi[32][72], a_lo[32][72];
  __shared__ float b_hi[32][72], b_lo[32][72];
  int blk = blockIdx.x;
  int b = blk / 400; int rem = blk % 400;
  int o0 = (rem / 100) * 64;
  int n0 = (rem % 100) * 64;
  int t = threadIdx.x;
  int warp = t >> 5, lane = t & 31;
  int wi = warp & 1, wj = warp >> 1;
  int g = lane >> 2, t4 = lane & 3;
  float C[2][2][4];
#pragma unroll
  for (int m = 0; m < 2; m++)
#pragma unroll
    for (int n = 0; n < 2; n++)
#pragma unroll
      for (int r = 0; r < 4; r++) C[m][n][r] = 0.f;

  for (int k0 = 0; k0 < 512; k0 += 32) {
#pragma unroll
    for (int r = 0; r < 8; r++) {
      int e = t + 256*r; int kk = e & 31, oo = e >> 5;
      int kg = k0 + kk;
      float wv = mlp_w[(o0+oo)*512 + kg];
      if (kg >= 256) wv *= catt1[kg-256];
      float h = tf32r(wv);
      a_hi[kk][oo] = h; a_lo[kk][oo] = tf32r(wv - h);
    }
    if (k0 < 256) {
#pragma unroll
      for (int r = 0; r < 8; r++) {
        int e = t + 256*r; int kk = e & 31, nn = e >> 5;
        float v = g_ovb[(b*HWN + n0+nn)*CC + k0+kk];
        float h = tf32r(v);
        b_hi[kk][nn] = h; b_lo[kk][nn] = tf32r(v - h);
      }
    } else {
#pragma unroll
      for (int r = 0; r < 8; r++) {
        int e = t + 256*r; int nn = e & 63, kk = e >> 6;
        float v = feat[(b*CC + (k0-256+kk))*HWN + n0+nn];
        float h = tf32r(v);
        b_hi[kk][nn] = h; b_lo[kk][nn] = tf32r(v - h);
      }
    }
    __syncthreads();
    unsigned Ah[2][4][4], Al[2][4][4];
#pragma unroll
    for (int m = 0; m < 2; m++) {
      int ib = wi*32 + m*16;
#pragma unroll
      for (int kt = 0; kt < 4; kt++) {
        int kb = kt*8;
        Ah[m][kt][0] = __float_as_uint(a_hi[kb+t4  ][ib+g  ]);
        Ah[m][kt][1] = __float_as_uint(a_hi[kb+t4  ][ib+g+8]);
        Ah[m][kt][2] = __float_as_uint(a_hi[kb+t4+4][ib+g  ]);
        Ah[m][kt][3] = __float_as_uint(a_hi[kb+t4+4][ib+g+8]);
        Al[m][kt][0] = __float_as_uint(a_lo[kb+t4  ][ib+g  ]);
        Al[m][kt][1] = __float_as_uint(a_lo[kb+t4  ][ib+g+8]);
        Al[m][kt][2] = __float_as_uint(a_lo[kb+t4+4][ib+g  ]);
        Al[m][kt][3] = __float_as_uint(a_lo[kb+t4+4][ib+g+8]);
      }
    }
#pragma unroll
    for (int n = 0; n < 2; n++) {
      int nb = wj*16 + n*8;
      unsigned Bh[4][2], Bl[4][2];
#pragma unroll
      for (int kt = 0; kt < 4; kt++) {
        Bh[kt][0] = __float_as_uint(b_hi[kt*8+t4  ][nb+g]);
        Bh[kt][1] = __float_as_uint(b_hi[kt*8+t4+4][nb+g]);
        Bl[kt][0] = __float_as_uint(b_lo[kt*8+t4  ][nb+g]);
        Bl[kt][1] = __float_as_uint(b_lo[kt*8+t4+4][nb+g]);
      }
#pragma unroll
      for (int m = 0; m < 2; m++) {
#pragma unroll
        for (int kt = 0; kt < 4; kt++) {
          mma_tf32(C[m][n][0],C[m][n][1],C[m][n][2],C[m][n][3],
                   Al[m][kt][0],Al[m][kt][1],Al[m][kt][2],Al[m][kt][3], Bh[kt][0],Bh[kt][1]);
          mma_tf32(C[m][n][0],C[m][n][1],C[m][n][2],C[m][n][3],
                   Ah[m][kt][0],Ah[m][kt][1],Ah[m][kt][2],Ah[m][kt][3], Bl[kt][0],Bl[kt][1]);
          mma_tf32(C[m][n][0],C[m][n][1],C[m][n][2],C[m][n][3],
                   Ah[m][kt][0],Ah[m][kt][1],Ah[m][kt][2],Ah[m][kt][3], Bh[kt][0],Bh[kt][1]);
        }
      }
    }
    __syncthreads();
  }
  const float bnadj = rsqrtf(1.0f + 1e-5f);
#pragma unroll
  for (int m = 0; m < 2; m++) {
    int oa = o0 + wi*32 + m*16 + g;
    int ob = oa + 8;
    float ga  = mlp_gamma[oa]*bnadj, ba = mlp_beta[oa], mba = mlp_b[oa];
    float gb2 = mlp_gamma[ob]*bnadj, bb = mlp_beta[ob], mbb = mlp_b[ob];
#pragma unroll
    for (int n = 0; n < 2; n++) {
      int nc = n0 + wj*16 + n*8 + 2*t4;
      float2 ra, rb;
      ra.x = fmaxf((C[m][n][0]+mba)*ga + ba, 0.f);
      ra.y = fmaxf((C[m][n][1]+mba)*ga + ba, 0.f);
      rb.x = fmaxf((C[m][n][2]+mbb)*gb2 + bb, 0.f);
      rb.y = fmaxf((C[m][n][3]+mbb)*gb2 + bb, 0.f);
      *(float2*)&xout[(b*CC + oa)*HWN + nc] = ra;
      *(float2*)&xout[(b*CC + ob)*HWN + nc] = rb;
    }
  }
}

// ---------------- K5: dsn head ----------------
__global__ void __launch_bounds__(256) dsn_kernel(
    const float* __restrict__ dsn_w, const float* __restrict__ dsn_b,
    const float* __restrict__ dsn_g, const float* __restrict__ dsn_beta,
    const float* __restrict__ x, float* __restrict__ r0) {
  __shared__ float ws[256];
  int blk = blockIdx.x;
  int b  = blk / 25;
  int n0 = (blk % 25) * 256;
  int t  = threadIdx.x;
  ws[t] = dsn_w[t];
  __syncthreads();
  int n = n0 + t;
  float acc = 0.f;
#pragma unroll 8
  for (int o = 0; o < 256; o++) acc += ws[o]*x[(b*CC+o)*HWN + n];
  float g = dsn_g[0]*rsqrtf(1.0f+1e-5f);
  r0[b*HWN + n] = fmaxf((acc + dsn_b[0])*g + dsn_beta[0], 0.f);
}

// ---------------- launch ----------------
extern "C" void kernel_launch(void* const* d_in, const int* in_sizes, int n_in,
                              void* d_out, int out_size) {
  const float* feat    = (const float*)d_in[0];
  const float* Wq      = (const float*)d_in[1];
  const float* Wk      = (const float*)d_in[2];
  const float* Wv      = (const float*)d_in[3];
  const float* adw     = (const float*)d_in[4];
  const float* adb     = (const float*)d_in[5];
  const float* pw1     = (const float*)d_in[6];
  const float* pw2     = (const float*)d_in[7];
  const float* backw   = (const float*)d_in[8];
  const float* catt    = (const float*)d_in[9];
  const float* catt1   = (const float*)d_in[10];
  const float* mlpw    = (const float*)d_in[11];
  const float* mlpb    = (const float*)d_in[12];
  const float* mlpg    = (const float*)d_in[13];
  const float* mlpbeta = (const float*)d_in[14];
  const float* dsnw    = (const float*)d_in[15];
  const float* dsnb    = (const float*)d_in[16];
  const float* dsng    = (const float*)d_in[17];
  const float* dsnbeta = (const float*)d_in[18];
  float* out = (float*)d_out;

  proj_kernel<<<400, 256>>>(feat, Wq, Wk, Wv);
  wtopk_kernel<<<BB*JSPLIT*100, 256>>>();
  post_kernel<<<1600, 256>>>(adw, adb, pw1, pw2, backw, catt);
  mlp_kernel<<<800, 256>>>(feat, mlpw, mlpb, mlpg, mlpbeta, catt1, out);
  dsn_kernel<<<50, 256>>>(dsnw, dsnb, dsng, dsnbeta, out, out + BB*CC*HWN);
}

// round 5
// speedup vs baseline: 1.2324x; 1.2324x over previous
#include <cuda_runtime.h>
#include <math.h>

#define BB 2
#define CC 256
#define HWN 6400
#define DD 32
#define PP 9

// ---------------- device scratch ----------------
__device__ float g_qn[BB*DD*HWN];        // [b][d][i]
__device__ float g_kn[BB*DD*HWN];        // [b][d][j]
__device__ float g_v [BB*HWN*DD];        // [b][j][d]
__device__ float g_pval[BB*2*HWN*36];    // 2 splits x 4 quad-lists x 9
__device__ int   g_pidx[BB*2*HWN*36];
__device__ float g_ovb[BB*CC*HWN];       // [b][c][n]
__device__ float g_mlpwT[512*256];       // [k][o], catt1 folded into k>=256

// ---------------- helpers ----------------
__device__ __forceinline__ float tf32r(float x) {
  unsigned y; asm("cvt.rna.tf32.f32 %0, %1;" : "=r"(y) : "f"(x));
  return __uint_as_float(y);
}
__device__ __forceinline__ void mma_tf32(
    float& c0, float& c1, float& c2, float& c3,
    unsigned a0, unsigned a1, unsigned a2, unsigned a3,
    unsigned b0, unsigned b1) {
  asm volatile("mma.sync.aligned.m16n8k8.row.col.f32.tf32.tf32.f32 "
    "{%0,%1,%2,%3},{%4,%5,%6,%7},{%8,%9},{%0,%1,%2,%3};"
    : "+f"(c0), "+f"(c1), "+f"(c2), "+f"(c3)
    : "r"(a0), "r"(a1), "r"(a2), "r"(a3), "r"(b0), "r"(b1));
}
__device__ __forceinline__ void cpa16(void* dst, const void* src) {
  unsigned ds = (unsigned)__cvta_generic_to_shared(dst);
  asm volatile("cp.async.cg.shared.global [%0], [%1], 16;\n" :: "r"(ds), "l"(src));
}
#define CPA_COMMIT() asm volatile("cp.async.commit_group;\n")
#define CPA_WAIT1()  asm volatile("cp.async.wait_group 1;\n")
#define CPA_WAIT0()  asm volatile("cp.async.wait_group 0;\n")

__device__ __forceinline__ void ins9(float (&tv)[9], int (&ti)[9], float v, int j) {
  if (v > tv[8]) {
    float cv = v; int cj = j;
#pragma unroll
    for (int s = 0; s < 9; s++) {
      bool gt = cv > tv[s];
      float nv = gt ? cv : tv[s]; int ni = gt ? cj : ti[s];
      float sv = gt ? tv[s] : cv; int si = gt ? ti[s] : cj;
      tv[s] = nv; ti[s] = ni; cv = sv; cj = si;
    }
  }
}

// ---------------- K0: fold catt1 into transposed mlp weights ----------------
__global__ void __launch_bounds__(256) prep_kernel(
    const float* __restrict__ mlp_w, const float* __restrict__ catt1) {
  int i = blockIdx.x*256 + threadIdx.x;   // 512 blocks -> 131072
  int o = i >> 9, k = i & 511;
  float v = mlp_w[i];
  if (k >= 256) v *= catt1[k-256];
  g_mlpwT[k*256 + o] = v;
}

// ---------------- K1: q,k,v projections + L2 normalize (fp32) ----------------
__global__ void __launch_bounds__(256) proj_kernel(
    const float* __restrict__ feat, const float* __restrict__ Wq,
    const float* __restrict__ Wk,   const float* __restrict__ Wv) {
  __shared__ float xs[64][33];
  __shared__ float ws[96][64];
  __shared__ float outs[96][33];
  __shared__ float scl[2][32];
  int blk = blockIdx.x;
  int b  = blk / 200;
  int n0 = (blk % 200) * 32;
  int t  = threadIdx.x;
  int n  = t & 31, dg = t >> 5;
  float acc[12];
#pragma unroll
  for (int u = 0; u < 12; u++) acc[u] = 0.f;

  for (int c0 = 0; c0 < CC; c0 += 64) {
#pragma unroll
    for (int r = 0; r < 8; r++) {
      int e = t + 256*r; int cl = e >> 5, nn = e & 31;
      xs[cl][nn] = feat[(b*CC + c0 + cl)*HWN + n0 + nn];
    }
#pragma unroll
    for (int r = 0; r < 24; r++) {
      int e = t + 256*r; int cl = e & 63, d = e >> 6;
      const float* Wp = (d < 32) ? Wq : ((d < 64) ? Wk : Wv);
      ws[d][cl] = Wp[(d & 31)*CC + c0 + cl];
    }
    __syncthreads();
#pragma unroll 4
    for (int cl = 0; cl < 64; cl += 4) {
      float x0 = xs[cl][n], x1 = xs[cl+1][n], x2 = xs[cl+2][n], x3 = xs[cl+3][n];
#pragma unroll
      for (int u = 0; u < 12; u++) {
        const float4 w4 = *(const float4*)&ws[dg*12+u][cl];
        acc[u] += w4.x*x0 + w4.y*x1 + w4.z*x2 + w4.w*x3;
      }
    }
    __syncthreads();
  }
#pragma unroll
  for (int u = 0; u < 12; u++) outs[dg*12+u][n] = acc[u];
  __syncthreads();
  if (t < 64) {
    int nn = t & 31, wh = t >> 5;
    float s = 0.f;
#pragma unroll
    for (int d = 0; d < 32; d++) { float v = outs[wh*32+d][nn]; s += v*v; }
    scl[wh][nn] = 1.f / fmaxf(sqrtf(s), 1e-12f);
  }
  __syncthreads();
#pragma unroll
  for (int r = 0; r < 4; r++) {
    int e = t + 256*r; int d = e >> 5, nn = e & 31;
    int off = (b*DD + d)*HWN + n0 + nn;
    g_qn[off] = outs[d][nn]    * scl[0][nn];
    g_kn[off] = outs[32+d][nn] * scl[1][nn];
  }
#pragma unroll
  for (int r = 0; r < 4; r++) {
    int e = t + 256*r; int d = e & 31, nn = e >> 5;
    g_v[(b*HWN + n0 + nn)*DD + d] = outs[64+d][nn];
  }
}

// ---------------- K2: w = qn @ kn^T (3xTF32) + register top-9 ----------------
// 128 threads, 4 warps. Block: 64 i x (50 j-tiles of 64). Warp tile 16x64.
// A (q) fragments persistent in registers; per-thread top-9 on C fragments.
__global__ void __launch_bounds__(128) wtopk_kernel() {
  __shared__ float qs[32][72];
  __shared__ float ks[2][32][72];
  int blk = blockIdx.x;
  int b = blk / 200; int rem = blk % 200;
  int split = rem / 100; int i0 = (rem % 100) * 64;
  int t = threadIdx.x;
  int w = t >> 5, lane = t & 31, g = lane >> 2, t4 = lane & 3;
  int ib = w*16;
  int jbase = split * 3200;

  // load q tile [k][i]
#pragma unroll
  for (int r = 0; r < 16; r++) {
    int e = t + 128*r; int i = e & 63, d = e >> 6;
    qs[d][i] = g_qn[(b*DD + d)*HWN + i0 + i];
  }
  __syncthreads();

  // persistent A fragments (hi/lo in registers)
  unsigned Ah[4][4], Al[4][4];
#pragma unroll
  for (int kt = 0; kt < 4; kt++) {
    int kb = kt*8;
    float v0 = qs[kb+t4  ][ib+g  ];
    float v1 = qs[kb+t4  ][ib+g+8];
    float v2 = qs[kb+t4+4][ib+g  ];
    float v3 = qs[kb+t4+4][ib+g+8];
    float h0 = tf32r(v0), h1 = tf32r(v1), h2 = tf32r(v2), h3 = tf32r(v3);
    Ah[kt][0] = __float_as_uint(h0); Al[kt][0] = __float_as_uint(tf32r(v0-h0));
    Ah[kt][1] = __float_as_uint(h1); Al[kt][1] = __float_as_uint(tf32r(v1-h1));
    Ah[kt][2] = __float_as_uint(h2); Al[kt][2] = __float_as_uint(tf32r(v2-h2));
    Ah[kt][3] = __float_as_uint(h3); Al[kt][3] = __float_as_uint(tf32r(v3-h3));
  }

  float tva[9], tvb[9]; int tia[9], tib[9];
#pragma unroll
  for (int s = 0; s < 9; s++) { tva[s] = -4.f; tvb[s] = -4.f; tia[s] = 0x7fffffff; tib[s] = 0x7fffffff; }

  // prefetch j-tile 0
#pragma unroll
  for (int r = 0; r < 4; r++) {
    int q = t + 128*r; int d = q >> 4; int jc = (q & 15)*4;
    cpa16(&ks[0][d][jc], &g_kn[(b*DD + d)*HWN + jbase + jc]);
  }
  CPA_COMMIT();

  for (int jt = 0; jt < 50; jt++) {
    int j0 = jbase + jt*64;
    if (jt + 1 < 50) {
      int jn = j0 + 64; int buf = (jt+1) & 1;
#pragma unroll
      for (int r = 0; r < 4; r++) {
        int q = t + 128*r; int d = q >> 4; int jc = (q & 15)*4;
        cpa16(&ks[buf][d][jc], &g_kn[(b*DD + d)*HWN + jn + jc]);
      }
      CPA_COMMIT();
      CPA_WAIT1();
    } else {
      CPA_WAIT0();
    }
    __syncthreads();
    const float (*kb_)[72] = ks[jt & 1];

    float Cf[8][4];
#pragma unroll
    for (int nf = 0; nf < 8; nf++)
#pragma unroll
      for (int r = 0; r < 4; r++) Cf[nf][r] = 0.f;

#pragma unroll
    for (int kt = 0; kt < 4; kt++) {
      int kk = kt*8;
#pragma unroll
      for (int nf = 0; nf < 8; nf++) {
        float bv0 = kb_[kk+t4  ][nf*8+g];
        float bv1 = kb_[kk+t4+4][nf*8+g];
        float bh0 = tf32r(bv0), bh1 = tf32r(bv1);
        unsigned Bh0 = __float_as_uint(bh0), Bh1 = __float_as_uint(bh1);
        unsigned Bl0 = __float_as_uint(tf32r(bv0-bh0)), Bl1 = __float_as_uint(tf32r(bv1-bh1));
        mma_tf32(Cf[nf][0],Cf[nf][1],Cf[nf][2],Cf[nf][3],
                 Al[kt][0],Al[kt][1],Al[kt][2],Al[kt][3], Bh0,Bh1);
        mma_tf32(Cf[nf][0],Cf[nf][1],Cf[nf][2],Cf[nf][3],
                 Ah[kt][0],Ah[kt][1],Ah[kt][2],Ah[kt][3], Bl0,Bl1);
        mma_tf32(Cf[nf][0],Cf[nf][1],Cf[nf][2],Cf[nf][3],
                 Ah[kt][0],Ah[kt][1],Ah[kt][2],Ah[kt][3], Bh0,Bh1);
      }
    }
    // per-thread top-9 insert (ascending j within the stream)
#pragma unroll
    for (int nf = 0; nf < 8; nf++) {
      int jc = j0 + nf*8 + 2*t4;
      ins9(tva, tia, Cf[nf][0], jc);
      ins9(tva, tia, Cf[nf][1], jc+1);
      ins9(tvb, tib, Cf[nf][2], jc);
      ins9(tvb, tib, Cf[nf][3], jc+1);
    }
    __syncthreads();
  }
  // write the 2 row-lists (slot = t4)
  int ra = i0 + ib + g;
  int basea = ((b*2 + split)*HWN + ra)*36 + t4*9;
  int baseb = basea + 8*36;
#pragma unroll
  for (int s = 0; s < 9; s++) {
    g_pval[basea+s] = tva[s]; g_pidx[basea+s] = tia[s];
    g_pval[baseb+s] = tvb[s]; g_pidx[baseb+s] = tib[s];
  }
}

// ---------------- K3: merge 8 lists + gate MLP + softmax + gather + back ----------------
__global__ void __launch_bounds__(256) post_kernel(
    const float* __restrict__ adw, const float* __restrict__ adb,
    const float* __restrict__ pw1, const float* __restrict__ pw2,
    const float* __restrict__ back_w, const float* __restrict__ catt) {
  __shared__ float back_s[256][33];
  __shared__ float w1s[162];
  __shared__ float w2s[162];
  __shared__ float wfin_s[8][12];
  __shared__ int   idx_s[8][12];
  __shared__ float sT[256][9];
  int blk = blockIdx.x;
  int b = blk / 800;
  int row0 = (blk % 800) * 8;
  int t = threadIdx.x;
#pragma unroll
  for (int r = 0; r < 32; r++) {
    int e = t + 256*r; int c = e >> 5, d = e & 31;
    back_s[c][d] = back_w[c*DD + d];
  }
  if (t < 162) { w1s[t] = pw1[t]; w2s[t] = pw2[t]; }
  __syncthreads();
  int wrp = t >> 5, lane = t & 31;
  int row = row0 + wrp;

  if (lane == 0) {
    float mv[9]; int mi[9];
#pragma unroll
    for (int s = 0; s < 9; s++) { mv[s] = -4.f; mi[s] = 0x7fffffff; }
    for (int sp = 0; sp < 2; sp++) {
      for (int L = 0; L < 4; L++) {
        int base = ((b*2 + sp)*HWN + row)*36 + L*9;
        for (int q = 0; q < 9; q++) {
          float v = g_pval[base+q];
          int   j = g_pidx[base+q];
          if (v < mv[8]) break;
          if (v > mv[8] || (v == mv[8] && j < mi[8])) {
            float cv = v; int cj = j;
#pragma unroll
            for (int s = 0; s < 9; s++) {
              bool bt = (cv > mv[s]) || (cv == mv[s] && cj < mi[s]);
              float nv = bt ? cv : mv[s]; int ni = bt ? cj : mi[s];
              float ov_ = bt ? mv[s] : cv; int oi = bt ? mi[s] : cj;
              mv[s]=nv; mi[s]=ni; cv=ov_; cj=oi;
            }
          }
        }
      }
    }
    float adwv = adw[0], adbv = adb[0];
    float xa[9], pos[9];
#pragma unroll
    for (int p = 0; p < 9; p++) { xa[p] = mv[p]*adwv + adbv; pos[p] = fmaxf(xa[p], 0.f); }
    float hdn[18];
#pragma unroll
    for (int q = 0; q < 18; q++) {
      float s = 0.f;
#pragma unroll
      for (int p = 0; p < 9; p++) s += w1s[q*9+p]*pos[p];
      hdn[q] = fmaxf(s, 0.f);
    }
    float z[9]; float zmax = -1e30f;
#pragma unroll
    for (int p = 0; p < 9; p++) { z[p] = (xa[p] > 0.f) ? xa[p] : -100000.0f; zmax = fmaxf(zmax, z[p]); }
    float es[9]; float esum = 0.f;
#pragma unroll
    for (int p = 0; p < 9; p++) { es[p] = expf(z[p]-zmax); esum += es[p]; }
    float inv = 1.f/esum;
#pragma unroll
    for (int p = 0; p < 9; p++) {
      float s = 0.f;
#pragma unroll
      for (int q = 0; q < 18; q++) s += w2s[p*18+q]*hdn[q];
      float msk = 1.f/(1.f+expf(-s));
      wfin_s[wrp][p] = es[p]*inv*msk;
      idx_s[wrp][p]  = mi[p];
    }
  }
  __syncwarp();
  float ov = 0.f;
#pragma unroll
  for (int p = 0; p < 9; p++)
    ov += wfin_s[wrp][p] * g_v[(b*HWN + idx_s[wrp][p])*DD + lane];
  float outc[8];
#pragma unroll
  for (int cc = 0; cc < 8; cc++) outc[cc] = 0.f;
#pragma unroll
  for (int d = 0; d < 32; d++) {
    float ovd = __shfl_sync(0xffffffffu, ov, d);
#pragma unroll
    for (int cc = 0; cc < 8; cc++) outc[cc] += back_s[cc*32+lane][d]*ovd;
  }
#pragma unroll
  for (int cc = 0; cc < 8; cc++) {
    int c = cc*32 + lane;
    sT[c][wrp] = outc[cc]*catt[c];
  }
  __syncthreads();
  // transposed write: [b][c][n], 8 consecutive n per thread
  float4 v0, v1;
  v0.x = sT[t][0]; v0.y = sT[t][1]; v0.z = sT[t][2]; v0.w = sT[t][3];
  v1.x = sT[t][4]; v1.y = sT[t][5]; v1.z = sT[t][6]; v1.w = sT[t][7];
  float* dst = &g_ovb[(b*CC + t)*HWN + row0];
  *(float4*)dst = v0;
  *(float4*)(dst+4) = v1;
}

// ---------------- K4: mlp GEMM (3xTF32, cp.async double-buffered) ----------------
// 128 threads, block 64o x 64n, warp tile 16x64, K=512 in 16 k-tiles of 32.
__global__ void __launch_bounds__(128) mlp_kernel(
    const float* __restrict__ feat, const float* __restrict__ mlp_b,
    const float* __restrict__ mlp_gamma, const float* __restrict__ mlp_beta,
    float* __restrict__ xout) {
  __shared__ float a_s[2][32][72];
  __shared__ float b_s[2][32][72];
  int blk = blockIdx.x;
  int b = blk / 400; int rem = blk % 400;
  int o0 = (rem / 100) * 64;
  int n0 = (rem % 100) * 64;
  int t = threadIdx.x;
  int w = t >> 5, lane = t & 31, g = lane >> 2, t4 = lane & 3;
  int ol = w*16;

  float Cf[8][4];
#pragma unroll
  for (int nf = 0; nf < 8; nf++)
#pragma unroll
    for (int r = 0; r < 4; r++) Cf[nf][r] = 0.f;

  const float* bbase = &g_ovb[(size_t)b*CC*HWN];
  const float* fbase = &feat[(size_t)b*CC*HWN];

  // prefetch k-tile 0
#pragma unroll
  for (int r = 0; r < 4; r++) {
    int q = t + 128*r; int kk = q >> 4; int xx = (q & 15)*4;
    cpa16(&a_s[0][kk][xx], &g_mlpwT[kk*256 + o0 + xx]);
    cpa16(&b_s[0][kk][xx], bbase + (size_t)kk*HWN + n0 + xx);
  }
  CPA_COMMIT();

  for (int kt = 0; kt < 16; kt++) {
    int k0 = kt*32;
    if (kt + 1 < 16) {
      int k1 = k0 + 32; int buf = (kt+1) & 1;
      const float* srcB = (k1 < 256) ? (bbase + (size_t)k1*HWN)
                                     : (fbase + (size_t)(k1-256)*HWN);
#pragma unroll
      for (int r = 0; r < 4; r++) {
        int q = t + 128*r; int kk = q >> 4; int xx = (q & 15)*4;
        cpa16(&a_s[buf][kk][xx], &g_mlpwT[(k1+kk)*256 + o0 + xx]);
        cpa16(&b_s[buf][kk][xx], srcB + (size_t)kk*HWN + n0 + xx);
      }
      CPA_COMMIT();
      CPA_WAIT1();
    } else {
      CPA_WAIT0();
    }
    __syncthreads();
    int buf = kt & 1;
    const float (*ab)[72] = a_s[buf];
    const float (*bb)[72] = b_s[buf];

    unsigned Ah[4][4], Al[4][4];
#pragma unroll
    for (int k8 = 0; k8 < 4; k8++) {
      int kb = k8*8;
      float v0 = ab[kb+t4  ][ol+g  ];
      float v1 = ab[kb+t4  ][ol+g+8];
      float v2 = ab[kb+t4+4][ol+g  ];
      float v3 = ab[kb+t4+4][ol+g+8];
      float h0 = tf32r(v0), h1 = tf32r(v1), h2 = tf32r(v2), h3 = tf32r(v3);
      Ah[k8][0] = __float_as_uint(h0); Al[k8][0] = __float_as_uint(tf32r(v0-h0));
      Ah[k8][1] = __float_as_uint(h1); Al[k8][1] = __float_as_uint(tf32r(v1-h1));
      Ah[k8][2] = __float_as_uint(h2); Al[k8][2] = __float_as_uint(tf32r(v2-h2));
      Ah[k8][3] = __float_as_uint(h3); Al[k8][3] = __float_as_uint(tf32r(v3-h3));
    }
#pragma unroll
    for (int k8 = 0; k8 < 4; k8++) {
      int kk = k8*8;
#pragma unroll
      for (int nf = 0; nf < 8; nf++) {
        float bv0 = bb[kk+t4  ][nf*8+g];
        float bv1 = bb[kk+t4+4][nf*8+g];
        float bh0 = tf32r(bv0), bh1 = tf32r(bv1);
        unsigned Bh0 = __float_as_uint(bh0), Bh1 = __float_as_uint(bh1);
        unsigned Bl0 = __float_as_uint(tf32r(bv0-bh0)), Bl1 = __float_as_uint(tf32r(bv1-bh1));
        mma_tf32(Cf[nf][0],Cf[nf][1],Cf[nf][2],Cf[nf][3],
                 Al[k8][0],Al[k8][1],Al[k8][2],Al[k8][3], Bh0,Bh1);
        mma_tf32(Cf[nf][0],Cf[nf][1],Cf[nf][2],Cf[nf][3],
                 Ah[k8][0],Ah[k8][1],Ah[k8][2],Ah[k8][3], Bl0,Bl1);
        mma_tf32(Cf[nf][0],Cf[nf][1],Cf[nf][2],Cf[nf][3],
                 Ah[k8][0],Ah[k8][1],Ah[k8][2],Ah[k8][3], Bh0,Bh1);
      }
    }
    __syncthreads();
  }
  // epilogue: bias + BN(eval) + relu
  const float bnadj = rsqrtf(1.0f + 1e-5f);
  int oa = o0 + ol + g;
  int ob = oa + 8;
  float ga  = mlp_gamma[oa]*bnadj, ba = mlp_beta[oa], mba = mlp_b[oa];
  float gb2 = mlp_gamma[ob]*bnadj, bb2 = mlp_beta[ob], mbb = mlp_b[ob];
#pragma unroll
  for (int nf = 0; nf < 8; nf++) {
    int nc = n0 + nf*8 + 2*t4;
    float2 ra, rb;
    ra.x = fmaxf((Cf[nf][0]+mba)*ga + ba, 0.f);
    ra.y = fmaxf((Cf[nf][1]+mba)*ga + ba, 0.f);
    rb.x = fmaxf((Cf[nf][2]+mbb)*gb2 + bb2, 0.f);
    rb.y = fmaxf((Cf[nf][3]+mbb)*gb2 + bb2, 0.f);
    *(float2*)&xout[((size_t)b*CC + oa)*HWN + nc] = ra;
    *(float2*)&xout[((size_t)b*CC + ob)*HWN + nc] = rb;
  }
}

// ---------------- K5: dsn head (split-o for parallelism) ----------------
__global__ void __launch_bounds__(256) dsn_kernel(
    const float* __restrict__ dsn_w, const float* __restrict__ dsn_b,
    const float* __restrict__ dsn_g, const float* __restrict__ dsn_beta,
    const float* __restrict__ x, float* __restrict__ r0) {
  __shared__ float ws[256];
  __shared__ float s2[2][128];
  int blk = blockIdx.x;
  int b  = blk / 50;
  int n0 = (blk % 50) * 128;
  int t  = threadIdx.x;
  ws[t] = dsn_w[t];
  __syncthreads();
  int nl = t & 127, half = t >> 7;
  int n = n0 + nl;
  float acc = 0.f;
  int obase = half*128;
#pragma unroll 8
  for (int o = 0; o < 128; o++) acc += ws[obase+o]*x[(b*CC+obase+o)*HWN + n];
  s2[half][nl] = acc;
  __syncthreads();
  if (t < 128) {
    float a = s2[0][t] + s2[1][t];
    float g = dsn_g[0]*rsqrtf(1.0f+1e-5f);
    r0[b*HWN + n0 + t] = fmaxf((a + dsn_b[0])*g + dsn_beta[0], 0.f);
  }
}

// ---------------- launch ----------------
extern "C" void kernel_launch(void* const* d_in, const int* in_sizes, int n_in,
                              void* d_out, int out_size) {
  const float* feat    = (const float*)d_in[0];
  const float* Wq      = (const float*)d_in[1];
  const float* Wk      = (const float*)d_in[2];
  const float* Wv      = (const float*)d_in[3];
  const float* adw     = (const float*)d_in[4];
  const float* adb     = (const float*)d_in[5];
  const float* pw1     = (const float*)d_in[6];
  const float* pw2     = (const float*)d_in[7];
  const float* backw   = (const float*)d_in[8];
  const float* catt    = (const float*)d_in[9];
  const float* catt1   = (const float*)d_in[10];
  const float* mlpw    = (const float*)d_in[11];
  const float* mlpb    = (const float*)d_in[12];
  const float* mlpg    = (const float*)d_in[13];
  const float* mlpbeta = (const float*)d_in[14];
  const float* dsnw    = (const float*)d_in[15];
  const float* dsnb    = (const float*)d_in[16];
  const float* dsng    = (const float*)d_in[17];
  const float* dsnbeta = (const float*)d_in[18];
  float* out = (float*)d_out;

  prep_kernel<<<512, 256>>>(mlpw, catt1);
  proj_kernel<<<400, 256>>>(feat, Wq, Wk, Wv);
  wtopk_kernel<<<400, 128>>>();
  post_kernel<<<1600, 256>>>(adw, adb, pw1, pw2, backw, catt);
  mlp_kernel<<<800, 128>>>(feat, mlpb, mlpg, mlpbeta, out);
  dsn_kernel<<<100, 256>>>(dsnw, dsnb, dsng, dsnbeta, out, out + BB*CC*HWN);
}

// round 6
// speedup vs baseline: 1.3435x; 1.0902x over previous
#include <cuda_runtime.h>
#include <math.h>

#define BB 2
#define CC 256
#define HWN 6400
#define DD 32
#define PP 9

// ---------------- device scratch ----------------
__device__ float g_qn[BB*DD*HWN];        // [b][d][i]
__device__ float g_kn[BB*DD*HWN];        // [b][d][j]
__device__ float g_v [BB*HWN*DD];        // [b][j][d]
__device__ float g_pval[BB*2*HWN*12];    // per (b,split,row): sorted top9, padded to 12
__device__ int   g_pidx[BB*2*HWN*12];
__device__ float g_ovb[BB*CC*HWN];       // [b][c][n]
__device__ float g_mlpwT[512*256];       // [k][o], catt1 folded into k>=256

// ---------------- helpers ----------------
__device__ __forceinline__ float tf32r(float x) {
  unsigned y; asm("cvt.rna.tf32.f32 %0, %1;" : "=r"(y) : "f"(x));
  return __uint_as_float(y);
}
__device__ __forceinline__ void mma_tf32(
    float& c0, float& c1, float& c2, float& c3,
    unsigned a0, unsigned a1, unsigned a2, unsigned a3,
    unsigned b0, unsigned b1) {
  asm volatile("mma.sync.aligned.m16n8k8.row.col.f32.tf32.tf32.f32 "
    "{%0,%1,%2,%3},{%4,%5,%6,%7},{%8,%9},{%0,%1,%2,%3};"
    : "+f"(c0), "+f"(c1), "+f"(c2), "+f"(c3)
    : "r"(a0), "r"(a1), "r"(a2), "r"(a3), "r"(b0), "r"(b1));
}
__device__ __forceinline__ void cpa16(void* dst, const void* src) {
  unsigned ds = (unsigned)__cvta_generic_to_shared(dst);
  asm volatile("cp.async.cg.shared.global [%0], [%1], 16;\n" :: "r"(ds), "l"(src));
}
#define CPA_COMMIT() asm volatile("cp.async.commit_group;\n")
#define CPA_WAIT1()  asm volatile("cp.async.wait_group 1;\n")
#define CPA_WAIT0()  asm volatile("cp.async.wait_group 0;\n")

__device__ __forceinline__ void ins9(float (&tv)[9], int (&ti)[9], float v, int j) {
  if (v > tv[8]) {
    float cv = v; int cj = j;
#pragma unroll
    for (int s = 0; s < 9; s++) {
      bool gt = cv > tv[s];
      float nv = gt ? cv : tv[s]; int ni = gt ? cj : ti[s];
      float sv = gt ? tv[s] : cv; int si = gt ? ti[s] : cj;
      tv[s] = nv; ti[s] = ni; cv = sv; cj = si;
    }
  }
}
// tie-aware insert (lower j wins on equal value)
__device__ __forceinline__ void ins9t(float (&mv)[9], int (&mi)[9], float v, int j) {
  if (v > mv[8] || (v == mv[8] && j < mi[8])) {
    float cv = v; int cj = j;
#pragma unroll
    for (int s = 0; s < 9; s++) {
      bool bt = (cv > mv[s]) || (cv == mv[s] && cj < mi[s]);
      float nv = bt ? cv : mv[s]; int ni = bt ? cj : mi[s];
      float ov_ = bt ? mv[s] : cv; int oi = bt ? mi[s] : cj;
      mv[s]=nv; mi[s]=ni; cv=ov_; cj=oi;
    }
  }
}

// ---------------- K0: fold catt1 into transposed mlp weights ----------------
__global__ void __launch_bounds__(256) prep_kernel(
    const float* __restrict__ mlp_w, const float* __restrict__ catt1) {
  int i = blockIdx.x*256 + threadIdx.x;
  int o = i >> 9, k = i & 511;
  float v = mlp_w[i];
  if (k >= 256) v *= catt1[k-256];
  g_mlpwT[k*256 + o] = v;
}

// ---------------- K1: q,k,v projections + L2 normalize (fp32) ----------------
__global__ void __launch_bounds__(256) proj_kernel(
    const float* __restrict__ feat, const float* __restrict__ Wq,
    const float* __restrict__ Wk,   const float* __restrict__ Wv) {
  __shared__ float xs[64][33];
  __shared__ float ws[96][64];
  __shared__ float outs[96][33];
  __shared__ float scl[2][32];
  int blk = blockIdx.x;
  int b  = blk / 200;
  int n0 = (blk % 200) * 32;
  int t  = threadIdx.x;
  int n  = t & 31, dg = t >> 5;
  float acc[12];
#pragma unroll
  for (int u = 0; u < 12; u++) acc[u] = 0.f;

  for (int c0 = 0; c0 < CC; c0 += 64) {
#pragma unroll
    for (int r = 0; r < 8; r++) {
      int e = t + 256*r; int cl = e >> 5, nn = e & 31;
      xs[cl][nn] = feat[(b*CC + c0 + cl)*HWN + n0 + nn];
    }
#pragma unroll
    for (int r = 0; r < 24; r++) {
      int e = t + 256*r; int cl = e & 63, d = e >> 6;
      const float* Wp = (d < 32) ? Wq : ((d < 64) ? Wk : Wv);
      ws[d][cl] = Wp[(d & 31)*CC + c0 + cl];
    }
    __syncthreads();
#pragma unroll 4
    for (int cl = 0; cl < 64; cl += 4) {
      float x0 = xs[cl][n], x1 = xs[cl+1][n], x2 = xs[cl+2][n], x3 = xs[cl+3][n];
#pragma unroll
      for (int u = 0; u < 12; u++) {
        const float4 w4 = *(const float4*)&ws[dg*12+u][cl];
        acc[u] += w4.x*x0 + w4.y*x1 + w4.z*x2 + w4.w*x3;
      }
    }
    __syncthreads();
  }
#pragma unroll
  for (int u = 0; u < 12; u++) outs[dg*12+u][n] = acc[u];
  __syncthreads();
  if (t < 64) {
    int nn = t & 31, wh = t >> 5;
    float s = 0.f;
#pragma unroll
    for (int d = 0; d < 32; d++) { float v = outs[wh*32+d][nn]; s += v*v; }
    scl[wh][nn] = 1.f / fmaxf(sqrtf(s), 1e-12f);
  }
  __syncthreads();
#pragma unroll
  for (int r = 0; r < 4; r++) {
    int e = t + 256*r; int d = e >> 5, nn = e & 31;
    int off = (b*DD + d)*HWN + n0 + nn;
    g_qn[off] = outs[d][nn]    * scl[0][nn];
    g_kn[off] = outs[32+d][nn] * scl[1][nn];
  }
#pragma unroll
  for (int r = 0; r < 4; r++) {
    int e = t + 256*r; int d = e & 31, nn = e >> 5;
    g_v[(b*HWN + n0 + nn)*DD + d] = outs[64+d][nn];
  }
}

// ---------------- K2: w = qn @ kn^T (3xTF32) + register top-9 + in-block merge ----------------
__global__ void __launch_bounds__(128) wtopk_kernel() {
  __shared__ float qs[32][72];
  __shared__ float ks[2][32][72];
  int blk = blockIdx.x;
  int b = blk / 200; int rem = blk % 200;
  int split = rem / 100; int i0 = (rem % 100) * 64;
  int t = threadIdx.x;
  int w = t >> 5, lane = t & 31, g = lane >> 2, t4 = lane & 3;
  int ib = w*16;
  int jbase = split * 3200;

#pragma unroll
  for (int r = 0; r < 16; r++) {
    int e = t + 128*r; int i = e & 63, d = e >> 6;
    qs[d][i] = g_qn[(b*DD + d)*HWN + i0 + i];
  }
  __syncthreads();

  unsigned Ah[4][4], Al[4][4];
#pragma unroll
  for (int kt = 0; kt < 4; kt++) {
    int kb = kt*8;
    float v0 = qs[kb+t4  ][ib+g  ];
    float v1 = qs[kb+t4  ][ib+g+8];
    float v2 = qs[kb+t4+4][ib+g  ];
    float v3 = qs[kb+t4+4][ib+g+8];
    float h0 = tf32r(v0), h1 = tf32r(v1), h2 = tf32r(v2), h3 = tf32r(v3);
    Ah[kt][0] = __float_as_uint(h0); Al[kt][0] = __float_as_uint(tf32r(v0-h0));
    Ah[kt][1] = __float_as_uint(h1); Al[kt][1] = __float_as_uint(tf32r(v1-h1));
    Ah[kt][2] = __float_as_uint(h2); Al[kt][2] = __float_as_uint(tf32r(v2-h2));
    Ah[kt][3] = __float_as_uint(h3); Al[kt][3] = __float_as_uint(tf32r(v3-h3));
  }

  float tva[9], tvb[9]; int tia[9], tib[9];
#pragma unroll
  for (int s = 0; s < 9; s++) { tva[s] = -4.f; tvb[s] = -4.f; tia[s] = 0x7fffffff; tib[s] = 0x7fffffff; }

#pragma unroll
  for (int r = 0; r < 4; r++) {
    int q = t + 128*r; int d = q >> 4; int jc = (q & 15)*4;
    cpa16(&ks[0][d][jc], &g_kn[(b*DD + d)*HWN + jbase + jc]);
  }
  CPA_COMMIT();

  for (int jt = 0; jt < 50; jt++) {
    int j0 = jbase + jt*64;
    if (jt + 1 < 50) {
      int jn = j0 + 64; int buf = (jt+1) & 1;
#pragma unroll
      for (int r = 0; r < 4; r++) {
        int q = t + 128*r; int d = q >> 4; int jc = (q & 15)*4;
        cpa16(&ks[buf][d][jc], &g_kn[(b*DD + d)*HWN + jn + jc]);
      }
      CPA_COMMIT();
      CPA_WAIT1();
    } else {
      CPA_WAIT0();
    }
    __syncthreads();
    const float (*kb_)[72] = ks[jt & 1];

    float Cf[8][4];
#pragma unroll
    for (int nf = 0; nf < 8; nf++)
#pragma unroll
      for (int r = 0; r < 4; r++) Cf[nf][r] = 0.f;

#pragma unroll
    for (int kt = 0; kt < 4; kt++) {
      int kk = kt*8;
#pragma unroll
      for (int nf = 0; nf < 8; nf++) {
        float bv0 = kb_[kk+t4  ][nf*8+g];
        float bv1 = kb_[kk+t4+4][nf*8+g];
        float bh0 = tf32r(bv0), bh1 = tf32r(bv1);
        unsigned Bh0 = __float_as_uint(bh0), Bh1 = __float_as_uint(bh1);
        unsigned Bl0 = __float_as_uint(tf32r(bv0-bh0)), Bl1 = __float_as_uint(tf32r(bv1-bh1));
        mma_tf32(Cf[nf][0],Cf[nf][1],Cf[nf][2],Cf[nf][3],
                 Al[kt][0],Al[kt][1],Al[kt][2],Al[kt][3], Bh0,Bh1);
        mma_tf32(Cf[nf][0],Cf[nf][1],Cf[nf][2],Cf[nf][3],
                 Ah[kt][0],Ah[kt][1],Ah[kt][2],Ah[kt][3], Bl0,Bl1);
        mma_tf32(Cf[nf][0],Cf[nf][1],Cf[nf][2],Cf[nf][3],
                 Ah[kt][0],Ah[kt][1],Ah[kt][2],Ah[kt][3], Bh0,Bh1);
      }
    }
#pragma unroll
    for (int nf = 0; nf < 8; nf++) {
      int jc = j0 + nf*8 + 2*t4;
      ins9(tva, tia, Cf[nf][0], jc);
      ins9(tva, tia, Cf[nf][1], jc+1);
      ins9(tvb, tib, Cf[nf][2], jc);
      ins9(tvb, tib, Cf[nf][3], jc+1);
    }
    __syncthreads();
  }

  // ---- in-block merge of the 4 quad-lists per row ----
  // reuse ks region: lv = 64 rows * 4 lists * 9 floats = 2304, li same in ints
  float* lv = &ks[0][0][0];
  int*   li = (int*)&ks[1][0][0];
  int ra = ib + g, rb = ib + 8 + g;
#pragma unroll
  for (int s = 0; s < 9; s++) {
    lv[(ra*4+t4)*9+s] = tva[s]; li[(ra*4+t4)*9+s] = tia[s];
    lv[(rb*4+t4)*9+s] = tvb[s]; li[(rb*4+t4)*9+s] = tib[s];
  }
  __syncthreads();
  if (t < 64) {
    float mv[9]; int mi[9];
#pragma unroll
    for (int s = 0; s < 9; s++) { mv[s] = -4.f; mi[s] = 0x7fffffff; }
    for (int L = 0; L < 4; L++) {
      int base = (t*4+L)*9;
      for (int q = 0; q < 9; q++) {
        float v = lv[base+q];
        if (v < mv[8]) break;
        ins9t(mv, mi, v, li[base+q]);
      }
    }
    int base = ((b*2 + split)*HWN + i0 + t)*12;
#pragma unroll
    for (int s = 0; s < 9; s++) { g_pval[base+s] = mv[s]; g_pidx[base+s] = mi[s]; }
  }
}

// ---------------- K3: phase-parallel post ----------------
// grid 400 (b x 200), block 256, 32 rows per block.
__global__ void __launch_bounds__(256) post_kernel(
    const float* __restrict__ adw, const float* __restrict__ adb,
    const float* __restrict__ pw1, const float* __restrict__ pw2,
    const float* __restrict__ back_w, const float* __restrict__ catt) {
  __shared__ float lv2[32][24];
  __shared__ int   li2[32][24];
  __shared__ float w1s[162];
  __shared__ float w2s[162];
  __shared__ float wfin_s[32][12];
  __shared__ int   idx_s[32][12];
  __shared__ float ovs[32][36];
  int blk = blockIdx.x;
  int b = blk / 200;
  int row0 = (blk % 200) * 32;
  int t = threadIdx.x;

  // back_w row for channel c=t into registers (L2-cached, 32KB table)
  float4 bw[8];
#pragma unroll
  for (int r = 0; r < 8; r++) bw[r] = *(const float4*)&back_w[t*DD + r*4];
  float cattc = catt[t];
  if (t < 162) { w1s[t] = pw1[t]; w2s[t] = pw2[t]; }

  // coalesced load of both splits' lists
#pragma unroll
  for (int r = 0; r < 3; r++) {
    int e = t + 256*r;            // < 768 = 32*24
    int row = e / 24, rr = e % 24;
    int sp = rr / 12, q = rr % 12;
    int gbase = ((b*2 + sp)*HWN + row0 + row)*12 + q;
    lv2[row][rr] = g_pval[gbase];
    li2[row][rr] = g_pidx[gbase];
  }
  __syncthreads();

  // Phase A: per-row merge(18) + gate MLP on threads 0..31
  if (t < 32) {
    float mv[9]; int mi[9];
#pragma unroll
    for (int s = 0; s < 9; s++) { mv[s] = -4.f; mi[s] = 0x7fffffff; }
    for (int sp = 0; sp < 2; sp++) {
      for (int q = 0; q < 9; q++) {
        float v = lv2[t][sp*12+q];
        if (v < mv[8]) break;
        ins9t(mv, mi, v, li2[t][sp*12+q]);
      }
    }
    float adwv = adw[0], adbv = adb[0];
    float xa[9], pos[9];
#pragma unroll
    for (int p = 0; p < 9; p++) { xa[p] = mv[p]*adwv + adbv; pos[p] = fmaxf(xa[p], 0.f); }
    float hdn[18];
#pragma unroll
    for (int q = 0; q < 18; q++) {
      float s = 0.f;
#pragma unroll
      for (int p = 0; p < 9; p++) s += w1s[q*9+p]*pos[p];
      hdn[q] = fmaxf(s, 0.f);
    }
    float z[9]; float zmax = -1e30f;
#pragma unroll
    for (int p = 0; p < 9; p++) { z[p] = (xa[p] > 0.f) ? xa[p] : -100000.0f; zmax = fmaxf(zmax, z[p]); }
    float es[9]; float esum = 0.f;
#pragma unroll
    for (int p = 0; p < 9; p++) { es[p] = expf(z[p]-zmax); esum += es[p]; }
    float inv = 1.f/esum;
#pragma unroll
    for (int p = 0; p < 9; p++) {
      float s = 0.f;
#pragma unroll
      for (int q = 0; q < 18; q++) s += w2s[p*18+q]*hdn[q];
      float msk = 1.f/(1.f+expf(-s));
      wfin_s[t][p] = es[p]*inv*msk;
      idx_s[t][p]  = mi[p];
    }
  }
  __syncthreads();

  // Phase B: gather ov[row][d] = sum_p wfin * v[idx[p]][d]; 8 threads/row, 4 d each
  {
    int row = t >> 3, dq = t & 7;
    float4 acc = make_float4(0.f, 0.f, 0.f, 0.f);
#pragma unroll
    for (int p = 0; p < 9; p++) {
      float wv = wfin_s[row][p];
      int j = idx_s[row][p];
      float4 v4 = *(const float4*)&g_v[((size_t)b*HWN + j)*DD + dq*4];
      acc.x += wv*v4.x; acc.y += wv*v4.y; acc.z += wv*v4.z; acc.w += wv*v4.w;
    }
    *(float4*)&ovs[row][dq*4] = acc;
  }
  __syncthreads();

  // Phase C: backproj; thread t = channel c; 32 rows
  float* dst = &g_ovb[((size_t)b*CC + t)*HWN + row0];
#pragma unroll
  for (int r4 = 0; r4 < 8; r4++) {
    float4 o4;
    float* o = (float*)&o4;
#pragma unroll
    for (int u = 0; u < 4; u++) {
      int row = r4*4 + u;
      float acc = 0.f;
#pragma unroll
      for (int d4 = 0; d4 < 8; d4++) {
        float4 v4 = *(const float4*)&ovs[row][d4*4];
        acc += bw[d4].x*v4.x + bw[d4].y*v4.y + bw[d4].z*v4.z + bw[d4].w*v4.w;
      }
      o[u] = acc * cattc;
    }
    *(float4*)&dst[r4*4] = o4;
  }
}

// ---------------- K4: mlp GEMM (3xTF32, cp.async double-buffered) ----------------
__global__ void __launch_bounds__(128) mlp_kernel(
    const float* __restrict__ feat, const float* __restrict__ mlp_b,
    const float* __restrict__ mlp_gamma, const float* __restrict__ mlp_beta,
    float* __restrict__ xout) {
  __shared__ float a_s[2][32][72];
  __shared__ float b_s[2][32][72];
  int blk = blockIdx.x;
  int b = blk / 400; int rem = blk % 400;
  int o0 = (rem / 100) * 64;
  int n0 = (rem % 100) * 64;
  int t = threadIdx.x;
  int w = t >> 5, lane = t & 31, g = lane >> 2, t4 = lane & 3;
  int ol = w*16;

  float Cf[8][4];
#pragma unroll
  for (int nf = 0; nf < 8; nf++)
#pragma unroll
    for (int r = 0; r < 4; r++) Cf[nf][r] = 0.f;

  const float* bbase = &g_ovb[(size_t)b*CC*HWN];
  const float* fbase = &feat[(size_t)b*CC*HWN];

#pragma unroll
  for (int r = 0; r < 4; r++) {
    int q = t + 128*r; int kk = q >> 4; int xx = (q & 15)*4;
    cpa16(&a_s[0][kk][xx], &g_mlpwT[kk*256 + o0 + xx]);
    cpa16(&b_s[0][kk][xx], bbase + (size_t)kk*HWN + n0 + xx);
  }
  CPA_COMMIT();

  for (int kt = 0; kt < 16; kt++) {
    int k0 = kt*32;
    if (kt + 1 < 16) {
      int k1 = k0 + 32; int buf = (kt+1) & 1;
      const float* srcB = (k1 < 256) ? (bbase + (size_t)k1*HWN)
                                     : (fbase + (size_t)(k1-256)*HWN);
#pragma unroll
      for (int r = 0; r < 4; r++) {
        int q = t + 128*r; int kk = q >> 4; int xx = (q & 15)*4;
        cpa16(&a_s[buf][kk][xx], &g_mlpwT[(k1+kk)*256 + o0 + xx]);
        cpa16(&b_s[buf][kk][xx], srcB + (size_t)kk*HWN + n0 + xx);
      }
      CPA_COMMIT();
      CPA_WAIT1();
    } else {
      CPA_WAIT0();
    }
    __syncthreads();
    int buf = kt & 1;
    const float (*ab)[72] = a_s[buf];
    const float (*bb)[72] = b_s[buf];

    unsigned Ah[4][4], Al[4][4];
#pragma unroll
    for (int k8 = 0; k8 < 4; k8++) {
      int kb = k8*8;
      float v0 = ab[kb+t4  ][ol+g  ];
      float v1 = ab[kb+t4  ][ol+g+8];
      float v2 = ab[kb+t4+4][ol+g  ];
      float v3 = ab[kb+t4+4][ol+g+8];
      float h0 = tf32r(v0), h1 = tf32r(v1), h2 = tf32r(v2), h3 = tf32r(v3);
      Ah[k8][0] = __float_as_uint(h0); Al[k8][0] = __float_as_uint(tf32r(v0-h0));
      Ah[k8][1] = __float_as_uint(h1); Al[k8][1] = __float_as_uint(tf32r(v1-h1));
      Ah[k8][2] = __float_as_uint(h2); Al[k8][2] = __float_as_uint(tf32r(v2-h2));
      Ah[k8][3] = __float_as_uint(h3); Al[k8][3] = __float_as_uint(tf32r(v3-h3));
    }
#pragma unroll
    for (int k8 = 0; k8 < 4; k8++) {
      int kk = k8*8;
#pragma unroll
      for (int nf = 0; nf < 8; nf++) {
        float bv0 = bb[kk+t4  ][nf*8+g];
        float bv1 = bb[kk+t4+4][nf*8+g];
        float bh0 = tf32r(bv0), bh1 = tf32r(bv1);
        unsigned Bh0 = __float_as_uint(bh0), Bh1 = __float_as_uint(bh1);
        unsigned Bl0 = __float_as_uint(tf32r(bv0-bh0)), Bl1 = __float_as_uint(tf32r(bv1-bh1));
        mma_tf32(Cf[nf][0],Cf[nf][1],Cf[nf][2],Cf[nf][3],
                 Al[k8][0],Al[k8][1],Al[k8][2],Al[k8][3], Bh0,Bh1);
        mma_tf32(Cf[nf][0],Cf[nf][1],Cf[nf][2],Cf[nf][3],
                 Ah[k8][0],Ah[k8][1],Ah[k8][2],Ah[k8][3], Bl0,Bl1);
        mma_tf32(Cf[nf][0],Cf[nf][1],Cf[nf][2],Cf[nf][3],
                 Ah[k8][0],Ah[k8][1],Ah[k8][2],Ah[k8][3], Bh0,Bh1);
      }
    }
    __syncthreads();
  }
  const float bnadj = rsqrtf(1.0f + 1e-5f);
  int oa = o0 + ol + g;
  int ob = oa + 8;
  float ga  = mlp_gamma[oa]*bnadj, ba = mlp_beta[oa], mba = mlp_b[oa];
  float gb2 = mlp_gamma[ob]*bnadj, bb2 = mlp_beta[ob], mbb = mlp_b[ob];
#pragma unroll
  for (int nf = 0; nf < 8; nf++) {
    int nc = n0 + nf*8 + 2*t4;
    float2 ra, rb;
    ra.x = fmaxf((Cf[nf][0]+mba)*ga + ba, 0.f);
    ra.y = fmaxf((Cf[nf][1]+mba)*ga + ba, 0.f);
    rb.x = fmaxf((Cf[nf][2]+mbb)*gb2 + bb2, 0.f);
    rb.y = fmaxf((Cf[nf][3]+mbb)*gb2 + bb2, 0.f);
    *(float2*)&xout[((size_t)b*CC + oa)*HWN + nc] = ra;
    *(float2*)&xout[((size_t)b*CC + ob)*HWN + nc] = rb;
  }
}

// ---------------- K5: dsn head ----------------
__global__ void __launch_bounds__(256) dsn_kernel(
    const float* __restrict__ dsn_w, const float* __restrict__ dsn_b,
    const float* __restrict__ dsn_g, const float* __restrict__ dsn_beta,
    const float* __restrict__ x, float* __restrict__ r0) {
  __shared__ float ws[256];
  __shared__ float s2[2][128];
  int blk = blockIdx.x;
  int b  = blk / 50;
  int n0 = (blk % 50) * 128;
  int t  = threadIdx.x;
  ws[t] = dsn_w[t];
  __syncthreads();
  int nl = t & 127, half = t >> 7;
  int n = n0 + nl;
  float acc = 0.f;
  int obase = half*128;
#pragma unroll 8
  for (int o = 0; o < 128; o++) acc += ws[obase+o]*x[(b*CC+obase+o)*HWN + n];
  s2[half][nl] = acc;
  __syncthreads();
  if (t < 128) {
    float a = s2[0][t] + s2[1][t];
    float g = dsn_g[0]*rsqrtf(1.0f+1e-5f);
    r0[b*HWN + n0 + t] = fmaxf((a + dsn_b[0])*g + dsn_beta[0], 0.f);
  }
}

// ---------------- launch ----------------
extern "C" void kernel_launch(void* const* d_in, const int* in_sizes, int n_in,
                              void* d_out, int out_size) {
  const float* feat    = (const float*)d_in[0];
  const float* Wq      = (const float*)d_in[1];
  const float* Wk      = (const float*)d_in[2];
  const float* Wv      = (const float*)d_in[3];
  const float* adw     = (const float*)d_in[4];
  const float* adb     = (const float*)d_in[5];
  const float* pw1     = (const float*)d_in[6];
  const float* pw2     = (const float*)d_in[7];
  const float* backw   = (const float*)d_in[8];
  const float* catt    = (const float*)d_in[9];
  const float* catt1   = (const float*)d_in[10];
  const float* mlpw    = (const float*)d_in[11];
  const float* mlpb    = (const float*)d_in[12];
  const float* mlpg    = (const float*)d_in[13];
  const float* mlpbeta = (const float*)d_in[14];
  const float* dsnw    = (const float*)d_in[15];
  const float* dsnb    = (const float*)d_in[16];
  const float* dsng    = (const float*)d_in[17];
  const float* dsnbeta = (const float*)d_in[18];
  float* out = (float*)d_out;

  prep_kernel<<<512, 256>>>(mlpw, catt1);
  proj_kernel<<<400, 256>>>(feat, Wq, Wk, Wv);
  wtopk_kernel<<<400, 128>>>();
  post_kernel<<<400, 256>>>(adw, adb, pw1, pw2, backw, catt);
  mlp_kernel<<<800, 128>>>(feat, mlpb, mlpg, mlpbeta, out);
  dsn_kernel<<<100, 256>>>(dsnw, dsnb, dsng, dsnbeta, out, out + BB*CC*HWN);
}

// round 7
// speedup vs baseline: 1.3659x; 1.0167x over previous
#include <cuda_runtime.h>
#include <math.h>

#define BB 2
#define CC 256
#define HWN 6400
#define DD 32
#define PP 9
#define JSP 4

// ---------------- device scratch ----------------
__device__ float g_qn[BB*DD*HWN];        // [b][d][i]
__device__ float g_kn[BB*DD*HWN];        // [b][d][j]
__device__ float g_v [BB*HWN*DD];        // [b][j][d]
__device__ float g_pval[BB*JSP*HWN*12];  // per (b,split,row): sorted top9 (pad 12)
__device__ int   g_pidx[BB*JSP*HWN*12];
__device__ float g_ovb[BB*CC*HWN];       // [b][c][n]
__device__ float g_mlpwT[512*256];       // [k][o], catt1 folded into k>=256

// ---------------- helpers ----------------
__device__ __forceinline__ void split2(float v, unsigned& h, unsigned& l) {
  unsigned hv = __float_as_uint(v) & 0xFFFFE000u;
  h = hv;
  l = __float_as_uint(v - __uint_as_float(hv));
}
__device__ __forceinline__ void mma_tf32(
    float& c0, float& c1, float& c2, float& c3,
    unsigned a0, unsigned a1, unsigned a2, unsigned a3,
    unsigned b0, unsigned b1) {
  asm volatile("mma.sync.aligned.m16n8k8.row.col.f32.tf32.tf32.f32 "
    "{%0,%1,%2,%3},{%4,%5,%6,%7},{%8,%9},{%0,%1,%2,%3};"
    : "+f"(c0), "+f"(c1), "+f"(c2), "+f"(c3)
    : "r"(a0), "r"(a1), "r"(a2), "r"(a3), "r"(b0), "r"(b1));
}
__device__ __forceinline__ void cpa16(void* dst, const void* src) {
  unsigned ds = (unsigned)__cvta_generic_to_shared(dst);
  asm volatile("cp.async.cg.shared.global [%0], [%1], 16;\n" :: "r"(ds), "l"(src));
}
#define CPA_COMMIT() asm volatile("cp.async.commit_group;\n")
#define CPA_WAIT1()  asm volatile("cp.async.wait_group 1;\n")
#define CPA_WAIT0()  asm volatile("cp.async.wait_group 0;\n")

__device__ __forceinline__ void ins9(float (&tv)[9], int (&ti)[9], float v, int j) {
  if (v > tv[8]) {
    float cv = v; int cj = j;
#pragma unroll
    for (int s = 0; s < 9; s++) {
      bool gt = cv > tv[s];
      float nv = gt ? cv : tv[s]; int ni = gt ? cj : ti[s];
      float sv = gt ? tv[s] : cv; int si = gt ? ti[s] : cj;
      tv[s] = nv; ti[s] = ni; cv = sv; cj = si;
    }
  }
}
__device__ __forceinline__ void ins9t(float (&mv)[9], int (&mi)[9], float v, int j) {
  if (v > mv[8] || (v == mv[8] && j < mi[8])) {
    float cv = v; int cj = j;
#pragma unroll
    for (int s = 0; s < 9; s++) {
      bool bt = (cv > mv[s]) || (cv == mv[s] && cj < mi[s]);
      float nv = bt ? cv : mv[s]; int ni = bt ? cj : mi[s];
      float ov_ = bt ? mv[s] : cv; int oi = bt ? mi[s] : cj;
      mv[s]=nv; mi[s]=ni; cv=ov_; cj=oi;
    }
  }
}

// ---------------- K0: fold catt1 into transposed mlp weights (split in 2) ----------------
__global__ void __launch_bounds__(256) prep_kernel(
    const float* __restrict__ mlp_w, const float* __restrict__ catt1, int base) {
  int i = base + blockIdx.x*256 + threadIdx.x;
  int o = i >> 9, k = i & 511;
  float v = mlp_w[i];
  if (k >= 256) v *= catt1[k-256];
  g_mlpwT[k*256 + o] = v;
}

// ---------------- K1: q,k,v projections + L2 normalize ----------------
__global__ void __launch_bounds__(256) proj_kernel(
    const float* __restrict__ feat, const float* __restrict__ Wq,
    const float* __restrict__ Wk,   const float* __restrict__ Wv) {
  __shared__ float xs[64][33];
  __shared__ float ws[96][64];
  __shared__ float outs[96][33];
  __shared__ float scl[2][32];
  int blk = blockIdx.x;
  int b  = blk / 200;
  int n0 = (blk % 200) * 32;
  int t  = threadIdx.x;
  int n  = t & 31, dg = t >> 5;
  float acc[12];
#pragma unroll
  for (int u = 0; u < 12; u++) acc[u] = 0.f;

  for (int c0 = 0; c0 < CC; c0 += 64) {
#pragma unroll
    for (int r = 0; r < 8; r++) {
      int e = t + 256*r; int cl = e >> 5, nn = e & 31;
      xs[cl][nn] = feat[(b*CC + c0 + cl)*HWN + n0 + nn];
    }
#pragma unroll
    for (int r = 0; r < 24; r++) {
      int e = t + 256*r; int cl = e & 63, d = e >> 6;
      const float* Wp = (d < 32) ? Wq : ((d < 64) ? Wk : Wv);
      ws[d][cl] = Wp[(d & 31)*CC + c0 + cl];
    }
    __syncthreads();
#pragma unroll 4
    for (int cl = 0; cl < 64; cl += 4) {
      float x0 = xs[cl][n], x1 = xs[cl+1][n], x2 = xs[cl+2][n], x3 = xs[cl+3][n];
#pragma unroll
      for (int u = 0; u < 12; u++) {
        const float4 w4 = *(const float4*)&ws[dg*12+u][cl];
        acc[u] += w4.x*x0 + w4.y*x1 + w4.z*x2 + w4.w*x3;
      }
    }
    __syncthreads();
  }
#pragma unroll
  for (int u = 0; u < 12; u++) outs[dg*12+u][n] = acc[u];
  __syncthreads();
  if (t < 64) {
    int nn = t & 31, wh = t >> 5;
    float s = 0.f;
#pragma unroll
    for (int d = 0; d < 32; d++) { float v = outs[wh*32+d][nn]; s += v*v; }
    scl[wh][nn] = 1.f / fmaxf(sqrtf(s), 1e-12f);
  }
  __syncthreads();
#pragma unroll
  for (int r = 0; r < 4; r++) {
    int e = t + 256*r; int d = e >> 5, nn = e & 31;
    int off = (b*DD + d)*HWN + n0 + nn;
    g_qn[off] = outs[d][nn]    * scl[0][nn];
    g_kn[off] = outs[32+d][nn] * scl[1][nn];
  }
#pragma unroll
  for (int r = 0; r < 4; r++) {
    int e = t + 256*r; int d = e & 31, nn = e >> 5;
    g_v[(b*HWN + n0 + nn)*DD + d] = outs[64+d][nn];
  }
}

// ---------------- K2: w = qn @ kn^T (3xTF32, trunc split) + reg top-9 + in-block merge ----------------
// grid 800: b(2) x split(4) x itile(100); 25 j-tiles of 64 per block.
__global__ void __launch_bounds__(128) wtopk_kernel() {
  __shared__ float qs[32][72];
  __shared__ float ks[2][32][72];
  int blk = blockIdx.x;
  int b = blk / (JSP*100); int rem = blk % (JSP*100);
  int split = rem / 100; int i0 = (rem % 100) * 64;
  int t = threadIdx.x;
  int w = t >> 5, lane = t & 31, g = lane >> 2, t4 = lane & 3;
  int ib = w*16;
  int jbase = split * (HWN/JSP);

#pragma unroll
  for (int r = 0; r < 16; r++) {
    int e = t + 128*r; int i = e & 63, d = e >> 6;
    qs[d][i] = g_qn[(b*DD + d)*HWN + i0 + i];
  }
  __syncthreads();

  unsigned Ah[4][4], Al[4][4];
#pragma unroll
  for (int kt = 0; kt < 4; kt++) {
    int kb = kt*8;
    split2(qs[kb+t4  ][ib+g  ], Ah[kt][0], Al[kt][0]);
    split2(qs[kb+t4  ][ib+g+8], Ah[kt][1], Al[kt][1]);
    split2(qs[kb+t4+4][ib+g  ], Ah[kt][2], Al[kt][2]);
    split2(qs[kb+t4+4][ib+g+8], Ah[kt][3], Al[kt][3]);
  }

  float tva[9], tvb[9]; int tia[9], tib[9];
#pragma unroll
  for (int s = 0; s < 9; s++) { tva[s] = -4.f; tvb[s] = -4.f; tia[s] = 0x7fffffff; tib[s] = 0x7fffffff; }

#pragma unroll
  for (int r = 0; r < 4; r++) {
    int q = t + 128*r; int d = q >> 4; int jc = (q & 15)*4;
    cpa16(&ks[0][d][jc], &g_kn[(b*DD + d)*HWN + jbase + jc]);
  }
  CPA_COMMIT();

  const int NT = HWN/JSP/64;   // 25
  for (int jt = 0; jt < NT; jt++) {
    int j0 = jbase + jt*64;
    if (jt + 1 < NT) {
      int jn = j0 + 64; int buf = (jt+1) & 1;
#pragma unroll
      for (int r = 0; r < 4; r++) {
        int q = t + 128*r; int d = q >> 4; int jc = (q & 15)*4;
        cpa16(&ks[buf][d][jc], &g_kn[(b*DD + d)*HWN + jn + jc]);
      }
      CPA_COMMIT();
      CPA_WAIT1();
    } else {
      CPA_WAIT0();
    }
    __syncthreads();
    const float (*kb_)[72] = ks[jt & 1];

    float Cf[8][4];
#pragma unroll
    for (int nf = 0; nf < 8; nf++)
#pragma unroll
      for (int r = 0; r < 4; r++) Cf[nf][r] = 0.f;

#pragma unroll
    for (int kt = 0; kt < 4; kt++) {
      int kk = kt*8;
#pragma unroll
      for (int nf = 0; nf < 8; nf++) {
        unsigned Bh0, Bl0, Bh1, Bl1;
        split2(kb_[kk+t4  ][nf*8+g], Bh0, Bl0);
        split2(kb_[kk+t4+4][nf*8+g], Bh1, Bl1);
        mma_tf32(Cf[nf][0],Cf[nf][1],Cf[nf][2],Cf[nf][3],
                 Al[kt][0],Al[kt][1],Al[kt][2],Al[kt][3], Bh0,Bh1);
        mma_tf32(Cf[nf][0],Cf[nf][1],Cf[nf][2],Cf[nf][3],
                 Ah[kt][0],Ah[kt][1],Ah[kt][2],Ah[kt][3], Bl0,Bl1);
        mma_tf32(Cf[nf][0],Cf[nf][1],Cf[nf][2],Cf[nf][3],
                 Ah[kt][0],Ah[kt][1],Ah[kt][2],Ah[kt][3], Bh0,Bh1);
      }
    }
#pragma unroll
    for (int nf = 0; nf < 8; nf++) {
      int jc = j0 + nf*8 + 2*t4;
      ins9(tva, tia, Cf[nf][0], jc);
      ins9(tva, tia, Cf[nf][1], jc+1);
      ins9(tvb, tib, Cf[nf][2], jc);
      ins9(tvb, tib, Cf[nf][3], jc+1);
    }
    __syncthreads();
  }

  // in-block merge of the 4 quad-lists per row
  float* lv = &ks[0][0][0];
  int*   li = (int*)&ks[1][0][0];
  int ra = ib + g, rb = ib + 8 + g;
#pragma unroll
  for (int s = 0; s < 9; s++) {
    lv[(ra*4+t4)*9+s] = tva[s]; li[(ra*4+t4)*9+s] = tia[s];
    lv[(rb*4+t4)*9+s] = tvb[s]; li[(rb*4+t4)*9+s] = tib[s];
  }
  __syncthreads();
  if (t < 64) {
    float mv[9]; int mi[9];
#pragma unroll
    for (int s = 0; s < 9; s++) { mv[s] = -4.f; mi[s] = 0x7fffffff; }
    for (int L = 0; L < 4; L++) {
      int base = (t*4+L)*9;
      for (int q = 0; q < 9; q++) {
        float v = lv[base+q];
        if (v < mv[8]) break;
        ins9t(mv, mi, v, li[base+q]);
      }
    }
    int base = ((b*JSP + split)*HWN + i0 + t)*12;
#pragma unroll
    for (int s = 0; s < 9; s++) { g_pval[base+s] = mv[s]; g_pidx[base+s] = mi[s]; }
  }
}

// ---------------- K3: phase-parallel post (merges JSP sorted lists) ----------------
__global__ void __launch_bounds__(256) post_kernel(
    const float* __restrict__ adw, const float* __restrict__ adb,
    const float* __restrict__ pw1, const float* __restrict__ pw2,
    const float* __restrict__ back_w, const float* __restrict__ catt) {
  __shared__ float lv2[32][48];
  __shared__ int   li2[32][48];
  __shared__ float w1s[162];
  __shared__ float w2s[162];
  __shared__ float wfin_s[32][12];
  __shared__ int   idx_s[32][12];
  __shared__ float ovs[32][36];
  int blk = blockIdx.x;
  int b = blk / 200;
  int row0 = (blk % 200) * 32;
  int t = threadIdx.x;

  float4 bw[8];
#pragma unroll
  for (int r = 0; r < 8; r++) bw[r] = *(const float4*)&back_w[t*DD + r*4];
  float cattc = catt[t];
  if (t < 162) { w1s[t] = pw1[t]; w2s[t] = pw2[t]; }

#pragma unroll
  for (int r = 0; r < 6; r++) {
    int e = t + 256*r;            // < 1536 = 32*48
    int row = e / 48, rr = e % 48;
    int sp = rr / 12, q = rr % 12;
    int gbase = ((b*JSP + sp)*HWN + row0 + row)*12 + q;
    lv2[row][rr] = g_pval[gbase];
    li2[row][rr] = g_pidx[gbase];
  }
  __syncthreads();

  if (t < 32) {
    float mv[9]; int mi[9];
#pragma unroll
    for (int s = 0; s < 9; s++) { mv[s] = -4.f; mi[s] = 0x7fffffff; }
    for (int sp = 0; sp < JSP; sp++) {
      for (int q = 0; q < 9; q++) {
        float v = lv2[t][sp*12+q];
        if (v < mv[8]) break;
        ins9t(mv, mi, v, li2[t][sp*12+q]);
      }
    }
    float adwv = adw[0], adbv = adb[0];
    float xa[9], pos[9];
#pragma unroll
    for (int p = 0; p < 9; p++) { xa[p] = mv[p]*adwv + adbv; pos[p] = fmaxf(xa[p], 0.f); }
    float hdn[18];
#pragma unroll
    for (int q = 0; q < 18; q++) {
      float s = 0.f;
#pragma unroll
      for (int p = 0; p < 9; p++) s += w1s[q*9+p]*pos[p];
      hdn[q] = fmaxf(s, 0.f);
    }
    float z[9]; float zmax = -1e30f;
#pragma unroll
    for (int p = 0; p < 9; p++) { z[p] = (xa[p] > 0.f) ? xa[p] : -100000.0f; zmax = fmaxf(zmax, z[p]); }
    float es[9]; float esum = 0.f;
#pragma unroll
    for (int p = 0; p < 9; p++) { es[p] = expf(z[p]-zmax); esum += es[p]; }
    float inv = 1.f/esum;
#pragma unroll
    for (int p = 0; p < 9; p++) {
      float s = 0.f;
#pragma unroll
      for (int q = 0; q < 18; q++) s += w2s[p*18+q]*hdn[q];
      float msk = 1.f/(1.f+expf(-s));
      wfin_s[t][p] = es[p]*inv*msk;
      idx_s[t][p]  = mi[p];
    }
  }
  __syncthreads();

  {
    int row = t >> 3, dq = t & 7;
    float4 acc = make_float4(0.f, 0.f, 0.f, 0.f);
#pragma unroll
    for (int p = 0; p < 9; p++) {
      float wv = wfin_s[row][p];
      int j = idx_s[row][p];
      float4 v4 = *(const float4*)&g_v[((size_t)b*HWN + j)*DD + dq*4];
      acc.x += wv*v4.x; acc.y += wv*v4.y; acc.z += wv*v4.z; acc.w += wv*v4.w;
    }
    *(float4*)&ovs[row][dq*4] = acc;
  }
  __syncthreads();

  float* dst = &g_ovb[((size_t)b*CC + t)*HWN + row0];
#pragma unroll
  for (int r4 = 0; r4 < 8; r4++) {
    float4 o4;
    float* o = (float*)&o4;
#pragma unroll
    for (int u = 0; u < 4; u++) {
      int row = r4*4 + u;
      float acc = 0.f;
#pragma unroll
      for (int d4 = 0; d4 < 8; d4++) {
        float4 v4 = *(const float4*)&ovs[row][d4*4];
        acc += bw[d4].x*v4.x + bw[d4].y*v4.y + bw[d4].z*v4.z + bw[d4].w*v4.w;
      }
      o[u] = acc * cattc;
    }
    *(float4*)&dst[r4*4] = o4;
  }
}

// ---------------- K4: mlp GEMM (3xTF32, trunc split, cp.async) ----------------
__global__ void __launch_bounds__(128) mlp_kernel(
    const float* __restrict__ feat, const float* __restrict__ mlp_b,
    const float* __restrict__ mlp_gamma, const float* __restrict__ mlp_beta,
    float* __restrict__ xout) {
  __shared__ float a_s[2][32][72];
  __shared__ float b_s[2][32][72];
  int blk = blockIdx.x;
  int b = blk / 400; int rem = blk % 400;
  int o0 = (rem / 100) * 64;
  int n0 = (rem % 100) * 64;
  int t = threadIdx.x;
  int w = t >> 5, lane = t & 31, g = lane >> 2, t4 = lane & 3;
  int ol = w*16;

  float Cf[8][4];
#pragma unroll
  for (int nf = 0; nf < 8; nf++)
#pragma unroll
    for (int r = 0; r < 4; r++) Cf[nf][r] = 0.f;

  const float* bbase = &g_ovb[(size_t)b*CC*HWN];
  const float* fbase = &feat[(size_t)b*CC*HWN];

#pragma unroll
  for (int r = 0; r < 4; r++) {
    int q = t + 128*r; int kk = q >> 4; int xx = (q & 15)*4;
    cpa16(&a_s[0][kk][xx], &g_mlpwT[kk*256 + o0 + xx]);
    cpa16(&b_s[0][kk][xx], bbase + (size_t)kk*HWN + n0 + xx);
  }
  CPA_COMMIT();

  for (int kt = 0; kt < 16; kt++) {
    int k0 = kt*32;
    if (kt + 1 < 16) {
      int k1 = k0 + 32; int buf = (kt+1) & 1;
      const float* srcB = (k1 < 256) ? (bbase + (size_t)k1*HWN)
                                     : (fbase + (size_t)(k1-256)*HWN);
#pragma unroll
      for (int r = 0; r < 4; r++) {
        int q = t + 128*r; int kk = q >> 4; int xx = (q & 15)*4;
        cpa16(&a_s[buf][kk][xx], &g_mlpwT[(k1+kk)*256 + o0 + xx]);
        cpa16(&b_s[buf][kk][xx], srcB + (size_t)kk*HWN + n0 + xx);
      }
      CPA_COMMIT();
      CPA_WAIT1();
    } else {
      CPA_WAIT0();
    }
    __syncthreads();
    int buf = kt & 1;
    const float (*ab)[72] = a_s[buf];
    const float (*bb)[72] = b_s[buf];

    unsigned Ah[4][4], Al[4][4];
#pragma unroll
    for (int k8 = 0; k8 < 4; k8++) {
      int kb = k8*8;
      split2(ab[kb+t4  ][ol+g  ], Ah[k8][0], Al[k8][0]);
      split2(ab[kb+t4  ][ol+g+8], Ah[k8][1], Al[k8][1]);
      split2(ab[kb+t4+4][ol+g  ], Ah[k8][2], Al[k8][2]);
      split2(ab[kb+t4+4][ol+g+8], Ah[k8][3], Al[k8][3]);
    }
#pragma unroll
    for (int k8 = 0; k8 < 4; k8++) {
      int kk = k8*8;
#pragma unroll
      for (int nf = 0; nf < 8; nf++) {
        unsigned Bh0, Bl0, Bh1, Bl1;
        split2(bb[kk+t4  ][nf*8+g], Bh0, Bl0);
        split2(bb[kk+t4+4][nf*8+g], Bh1, Bl1);
        mma_tf32(Cf[nf][0],Cf[nf][1],Cf[nf][2],Cf[nf][3],
                 Al[k8][0],Al[k8][1],Al[k8][2],Al[k8][3], Bh0,Bh1);
        mma_tf32(Cf[nf][0],Cf[nf][1],Cf[nf][2],Cf[nf][3],
                 Ah[k8][0],Ah[k8][1],Ah[k8][2],Ah[k8][3], Bl0,Bl1);
        mma_tf32(Cf[nf][0],Cf[nf][1],Cf[nf][2],Cf[nf][3],
                 Ah[k8][0],Ah[k8][1],Ah[k8][2],Ah[k8][3], Bh0,Bh1);
      }
    }
    __syncthreads();
  }
  const float bnadj = rsqrtf(1.0f + 1e-5f);
  int oa = o0 + ol + g;
  int ob = oa + 8;
  float ga  = mlp_gamma[oa]*bnadj, ba = mlp_beta[oa], mba = mlp_b[oa];
  float gb2 = mlp_gamma[ob]*bnadj, bb2 = mlp_beta[ob], mbb = mlp_b[ob];
#pragma unroll
  for (int nf = 0; nf < 8; nf++) {
    int nc = n0 + nf*8 + 2*t4;
    float2 ra, rb;
    ra.x = fmaxf((Cf[nf][0]+mba)*ga + ba, 0.f);
    ra.y = fmaxf((Cf[nf][1]+mba)*ga + ba, 0.f);
    rb.x = fmaxf((Cf[nf][2]+mbb)*gb2 + bb2, 0.f);
    rb.y = fmaxf((Cf[nf][3]+mbb)*gb2 + bb2, 0.f);
    *(float2*)&xout[((size_t)b*CC + oa)*HWN + nc] = ra;
    *(float2*)&xout[((size_t)b*CC + ob)*HWN + nc] = rb;
  }
}

// ---------------- K5: dsn head ----------------
__global__ void __launch_bounds__(256) dsn_kernel(
    const float* __restrict__ dsn_w, const float* __restrict__ dsn_b,
    const float* __restrict__ dsn_g, const float* __restrict__ dsn_beta,
    const float* __restrict__ x, float* __restrict__ r0) {
  __shared__ float ws[256];
  __shared__ float s2[2][128];
  int blk = blockIdx.x;
  int b  = blk / 50;
  int n0 = (blk % 50) * 128;
  int t  = threadIdx.x;
  ws[t] = dsn_w[t];
  __syncthreads();
  int nl = t & 127, half = t >> 7;
  int n = n0 + nl;
  float acc = 0.f;
  int obase = half*128;
#pragma unroll 8
  for (int o = 0; o < 128; o++) acc += ws[obase+o]*x[(b*CC+obase+o)*HWN + n];
  s2[half][nl] = acc;
  __syncthreads();
  if (t < 128) {
    float a = s2[0][t] + s2[1][t];
    float g = dsn_g[0]*rsqrtf(1.0f+1e-5f);
    r0[b*HWN + n0 + t] = fmaxf((a + dsn_b[0])*g + dsn_beta[0], 0.f);
  }
}

// ---------------- launch ----------------
extern "C" void kernel_launch(void* const* d_in, const int* in_sizes, int n_in,
                              void* d_out, int out_size) {
  const float* feat    = (const float*)d_in[0];
  const float* Wq      = (const float*)d_in[1];
  const float* Wk      = (const float*)d_in[2];
  const float* Wv      = (const float*)d_in[3];
  const float* adw     = (const float*)d_in[4];
  const float* adb     = (const float*)d_in[5];
  const float* pw1     = (const float*)d_in[6];
  const float* pw2     = (const float*)d_in[7];
  const float* backw   = (const float*)d_in[8];
  const float* catt    = (const float*)d_in[9];
  const float* catt1   = (const float*)d_in[10];
  const float* mlpw    = (const float*)d_in[11];
  const float* mlpb    = (const float*)d_in[12];
  const float* mlpg    = (const float*)d_in[13];
  const float* mlpbeta = (const float*)d_in[14];
  const float* dsnw    = (const float*)d_in[15];
  const float* dsnb    = (const float*)d_in[16];
  const float* dsng    = (const float*)d_in[17];
  const float* dsnbeta = (const float*)d_in[18];
  float* out = (float*)d_out;

  // order chosen so wtopk is launch index 3 (the slot ncu captures)
  proj_kernel<<<400, 256>>>(feat, Wq, Wk, Wv);
  prep_kernel<<<256, 256>>>(mlpw, catt1, 0);
  prep_kernel<<<256, 256>>>(mlpw, catt1, 65536);
  wtopk_kernel<<<BB*JSP*100, 128>>>();
  post_kernel<<<400, 256>>>(adw, adb, pw1, pw2, backw, catt);
  mlp_kernel<<<800, 128>>>(feat, mlpb, mlpg, mlpbeta, out);
  dsn_kernel<<<100, 256>>>(dsnw, dsnb, dsng, dsnbeta, out, out + BB*CC*HWN);
}